// round 7
// baseline (speedup 1.0000x reference)
#include <cuda_runtime.h>
#include <math.h>

// Problem constants
#define ROWS   49152      // B*T*N = 8*12*512
#define DCH    128        // D
#define NNODES 512        // N
#define NBT    96         // B*T
#define NH     4          // heads (d)
#define MBLK   384        // ROWS / 128

// attention smem pads
#define KTPAD 520         // Kt row stride (unsigned), [32][520]
#define VSPAD 40          // Vs row stride, [512][40]  (8tg+g conflict-free)
#define AQPAD 36          // Asq row stride, [256][36]

// ---------------- scratch (device globals; no cudaMalloc allowed) ----------
__device__ float    g_qraw[ROWS * DCH];
__device__ float    g_kraw[ROWS * DCH];
__device__ float    g_vraw[ROWS * DCH];
__device__ float    g_aout[ROWS * DCH];
__device__ float    g_oraw[ROWS * DCH];
__device__ unsigned g_mask[NNODES * 16];      // A>0 bitmap: row n, 16 words
// deterministic BN partials: [z in 0..3][block 0..383][ch 0..127]
__device__ float g_psum[4 * MBLK * DCH];
__device__ float g_psumsq[4 * MBLK * DCH];
__device__ float g_scale[4 * DCH];
__device__ float g_shift[4 * DCH];

// ---------------- helpers ----------------------------------------------------
__device__ __forceinline__ unsigned f2tf32(float f) {
    unsigned r;
    asm("cvt.rna.tf32.f32 %0, %1;" : "=r"(r) : "f"(f));
    return r;
}

__device__ __forceinline__ void split_tf32(float v, unsigned& h, unsigned& l) {
    h = f2tf32(v);
    l = f2tf32(v - __uint_as_float(h));
}

__device__ __forceinline__ void mma_tf32(float* c, const unsigned* a, const unsigned* b) {
    asm volatile(
        "mma.sync.aligned.m16n8k8.row.col.f32.tf32.tf32.f32 "
        "{%0,%1,%2,%3}, {%4,%5,%6,%7}, {%8,%9}, {%0,%1,%2,%3};\n"
        : "+f"(c[0]), "+f"(c[1]), "+f"(c[2]), "+f"(c[3])
        : "r"(a[0]), "r"(a[1]), "r"(a[2]), "r"(a[3]), "r"(b[0]), "r"(b[1]));
}

// ---------------- adjacency bitmap (warp per row, ballot) --------------------
__global__ void build_mask_kernel(const float* __restrict__ A)
{
    int row  = (blockIdx.x * blockDim.x + threadIdx.x) >> 5;
    int lane = threadIdx.x & 31;
    if (row >= NNODES) return;
    for (int w = 0; w < 16; w++) {
        float a = A[row * NNODES + w * 32 + lane];
        unsigned bal = __ballot_sync(0xffffffffu, a > 0.f);
        if (lane == 0) g_mask[row * 16 + w] = bal;
    }
}

// ---------------- split-tf32 tensor GEMM, 128x128 tile, BK=32 ---------------
// Y = A @ W with 3-term tf32 error compensation (hi*hi + lo*hi + hi*lo) ->
// ~fp32 accuracy. Bias dropped (cancels in BatchNorm). CAT: A=[X|STE], K=256.
// Fused epilogue: per-CTA per-channel sum/sumsq partials.
template <int KDIM, bool CAT>
__global__ __launch_bounds__(256)
void mma_gemm_kernel(const float* __restrict__ A0, const float* __restrict__ A1,
                     const float* __restrict__ W0, const float* __restrict__ W1,
                     const float* __restrict__ W2,
                     float* __restrict__ Y0, float* __restrict__ Y1,
                     float* __restrict__ Y2, int zbase)
{
    __shared__ unsigned AsH[128 * 36], AsL[128 * 36];
    __shared__ unsigned BsH[32 * 136], BsL[32 * 136];
    __shared__ float ssum[2][128], ssq[2][128];

    const int z = blockIdx.z;
    const float* W = (z == 0) ? W0 : (z == 1) ? W1 : W2;
    float*       Y = (z == 0) ? Y0 : (z == 1) ? Y1 : Y2;

    const int tid  = threadIdx.x;
    const int lane = tid & 31;
    const int wid  = tid >> 5;
    const int wm   = wid >> 2;
    const int wn   = wid & 3;
    const int row0 = blockIdx.x * 128;
    const int g    = lane >> 2;
    const int tg   = lane & 3;

    float acc[4][4][4];
#pragma unroll
    for (int mt = 0; mt < 4; mt++)
#pragma unroll
        for (int nt = 0; nt < 4; nt++)
#pragma unroll
            for (int q = 0; q < 4; q++) acc[mt][nt][q] = 0.f;

    for (int k0 = 0; k0 < KDIM; k0 += 32) {
        const float* Abase;
        int kofs;
        if (CAT) {
            if (k0 < 128) { Abase = A0; kofs = k0; }
            else          { Abase = A1; kofs = k0 - 128; }
        } else { Abase = A0; kofs = k0; }

#pragma unroll
        for (int t = 0; t < 4; t++) {
            int i  = tid + 256 * t;
            int r  = i >> 3;
            int kq = (i & 7) << 2;
            float4 v = *(const float4*)(Abase + (size_t)(row0 + r) * 128 + kofs + kq);
            int o = r * 36 + kq;
            split_tf32(v.x, AsH[o + 0], AsL[o + 0]);
            split_tf32(v.y, AsH[o + 1], AsL[o + 1]);
            split_tf32(v.z, AsH[o + 2], AsL[o + 2]);
            split_tf32(v.w, AsH[o + 3], AsL[o + 3]);
        }
#pragma unroll
        for (int t = 0; t < 4; t++) {
            int i  = tid + 256 * t;
            int k  = i >> 5;
            int n4 = (i & 31) << 2;
            float4 v = *(const float4*)(W + (size_t)(k0 + k) * 128 + n4);
            int o = k * 136 + n4;
            split_tf32(v.x, BsH[o + 0], BsL[o + 0]);
            split_tf32(v.y, BsH[o + 1], BsL[o + 1]);
            split_tf32(v.z, BsH[o + 2], BsL[o + 2]);
            split_tf32(v.w, BsH[o + 3], BsL[o + 3]);
        }
        __syncthreads();

#pragma unroll
        for (int ks = 0; ks < 4; ks++) {
            const int kb = ks * 8;
#pragma unroll
            for (int term = 0; term < 3; term++) {
                const unsigned* Ap = (term == 1) ? AsL : AsH;
                const unsigned* Bp = (term == 2) ? BsL : BsH;
                unsigned af[4][4];
#pragma unroll
                for (int mt = 0; mt < 4; mt++) {
                    int r = wm * 64 + mt * 16 + g;
                    af[mt][0] = Ap[r * 36 + kb + tg];
                    af[mt][1] = Ap[(r + 8) * 36 + kb + tg];
                    af[mt][2] = Ap[r * 36 + kb + tg + 4];
                    af[mt][3] = Ap[(r + 8) * 36 + kb + tg + 4];
                }
#pragma unroll
                for (int nt = 0; nt < 4; nt++) {
                    int cc = wn * 32 + nt * 8 + g;
                    unsigned bf[2];
                    bf[0] = Bp[(kb + tg) * 136 + cc];
                    bf[1] = Bp[(kb + tg + 4) * 136 + cc];
#pragma unroll
                    for (int mt = 0; mt < 4; mt++)
                        mma_tf32(acc[mt][nt], af[mt], bf);
                }
            }
        }
        __syncthreads();
    }

#pragma unroll
    for (int nt = 0; nt < 4; nt++) {
        float se = 0.f, so = 0.f, qe = 0.f, qo = 0.f;
#pragma unroll
        for (int mt = 0; mt < 4; mt++) {
            float c0 = acc[mt][nt][0], c1 = acc[mt][nt][1];
            float c2 = acc[mt][nt][2], c3 = acc[mt][nt][3];
            int r   = row0 + wm * 64 + mt * 16 + g;
            int col = wn * 32 + nt * 8 + tg * 2;
            *(float2*)(Y + (size_t)r * 128 + col)       = make_float2(c0, c1);
            *(float2*)(Y + (size_t)(r + 8) * 128 + col) = make_float2(c2, c3);
            se += c0 + c2;  so += c1 + c3;
            qe += c0 * c0 + c2 * c2;  qo += c1 * c1 + c3 * c3;
        }
#pragma unroll
        for (int o = 4; o < 32; o <<= 1) {
            se += __shfl_xor_sync(0xffffffffu, se, o);
            so += __shfl_xor_sync(0xffffffffu, so, o);
            qe += __shfl_xor_sync(0xffffffffu, qe, o);
            qo += __shfl_xor_sync(0xffffffffu, qo, o);
        }
        if (lane < 4) {
            int col = wn * 32 + nt * 8 + lane * 2;
            ssum[wm][col]     = se;  ssum[wm][col + 1] = so;
            ssq[wm][col]      = qe;  ssq[wm][col + 1]  = qo;
        }
    }
    __syncthreads();
    if (tid < 128) {
        int slot = ((zbase + z) * MBLK + blockIdx.x) * DCH + tid;
        g_psum[slot]   = ssum[0][tid] + ssum[1][tid];
        g_psumsq[slot] = ssq[0][tid] + ssq[1][tid];
    }
}

// ---------------- BN finalize: reduce 384 partials (parallel) ---------------
__global__ void bn_finalize_kernel(const float* __restrict__ g0, const float* __restrict__ be0,
                                   const float* __restrict__ g1, const float* __restrict__ be1,
                                   const float* __restrict__ g2, const float* __restrict__ be2,
                                   int zbase)
{
    __shared__ float ss[512], sq[512];
    int z = blockIdx.x;
    const float* g  = (z == 0) ? g0 : (z == 1) ? g1 : g2;
    const float* be = (z == 0) ? be0 : (z == 1) ? be1 : be2;
    int ch = threadIdx.x & 127, part = threadIdx.x >> 7;
    float s = 0.f, s2 = 0.f;
    for (int b = part; b < MBLK; b += 4) {
        int slot = ((zbase + z) * MBLK + b) * DCH + ch;
        s  += g_psum[slot];
        s2 += g_psumsq[slot];
    }
    ss[threadIdx.x] = s;  sq[threadIdx.x] = s2;
    __syncthreads();
    if (threadIdx.x < 128) {
        s  = ss[ch] + ss[ch + 128] + ss[ch + 256] + ss[ch + 384];
        s2 = sq[ch] + sq[ch + 128] + sq[ch + 256] + sq[ch + 384];
        const float inv_cnt = 1.f / (float)ROWS;
        float mu  = s * inv_cnt;
        float var = s2 * inv_cnt - mu * mu;
        float sc  = g[ch] * rsqrtf(var + 1e-5f);
        g_scale[(zbase + z) * 128 + ch] = sc;
        g_shift[(zbase + z) * 128 + ch] = be[ch] - mu * sc;
    }
}

// ---------------- dense tensor-core masked flash-attention v3 ---------------
// One CTA per (bt, head); 512 threads = 16 warps; warp owns 16 query rows of
// a 256-row super-tile (2 super-tiles / CTA). Q A-frags hoisted across the kv
// loop. No running max: q,k >= 0 ==> s in [0, bounded], p = exp(s/2 - 30)
// cannot overflow and masked terms are exact 0 (matches the NEG fill).
// P goes accumulator->A-operand layout via register shfl transpose (no smem).
__global__ __launch_bounds__(512)
void attn_mma_kernel()
{
    extern __shared__ unsigned smu[];
    unsigned* Kt  = smu;                          // [32][KTPAD]  K^T tf32
    unsigned* Vs  = Kt  + 32 * KTPAD;             // [512][VSPAD] V tf32
    unsigned* Asq = Vs  + NNODES * VSPAD;         // [256][AQPAD] Q tile tf32
    unsigned* smk = Asq + 256 * AQPAD;            // [512][16] mask bitmap

    const int bt   = blockIdx.x;
    const int h    = blockIdx.y;
    const int tid  = threadIdx.x;
    const int lane = tid & 31;
    const int wid  = tid >> 5;                    // 0..15
    const int g    = lane >> 2;
    const int tg   = lane & 3;
    const size_t rowbase = (size_t)bt * NNODES;
    const int cb = h * 32;

    const float scq = g_scale[0 * 128 + cb + lane], shq = g_shift[0 * 128 + cb + lane];
    const float sck = g_scale[1 * 128 + cb + lane], shk = g_shift[1 * 128 + cb + lane];
    const float scv = g_scale[2 * 128 + cb + lane], shv = g_shift[2 * 128 + cb + lane];

    // stage K^T, V (BN+ReLU fused, tf32) and mask
    for (int idx = tid; idx < NNODES * 32; idx += 512) {
        int n = idx >> 5;                         // (idx & 31) == lane
        float kv = g_kraw[(rowbase + n) * 128 + cb + lane];
        Kt[lane * KTPAD + n] = f2tf32(fmaxf(0.f, fmaf(kv, sck, shk)));
        float vv = g_vraw[(rowbase + n) * 128 + cb + lane];
        Vs[n * VSPAD + lane] = f2tf32(fmaxf(0.f, fmaf(vv, scv, shv)));
    }
    for (int idx = tid; idx < NNODES * 16; idx += 512) smk[idx] = g_mask[idx];
    __syncthreads();

    const int q0 = wid * 16;
    const int src  = 4 * g + (tg >> 1);   // shfl transpose source lanes
    const int src2 = src + 2;
    const bool odd = (tg & 1);

    for (int qt = 0; qt < 2; qt++) {
        // stage this 256-row q super-tile
        for (int idx = tid; idx < 256 * 32; idx += 512) {
            int r = idx >> 5;
            float qv = g_qraw[(rowbase + qt * 256 + r) * 128 + cb + lane];
            Asq[r * AQPAD + lane] = f2tf32(fmaxf(0.f, fmaf(qv, scq, shq)));
        }
        __syncthreads();

        const int r0 = qt * 256 + q0 + g;
        const int r1 = r0 + 8;

        // hoist Q fragments (invariant across kv tiles)
        unsigned aq[4][4];
#pragma unroll
        for (int ks = 0; ks < 4; ks++) {
            const int kb = ks * 8;
            aq[ks][0] = Asq[(q0 + g) * AQPAD + kb + tg];
            aq[ks][1] = Asq[(q0 + g + 8) * AQPAD + kb + tg];
            aq[ks][2] = Asq[(q0 + g) * AQPAD + kb + tg + 4];
            aq[ks][3] = Asq[(q0 + g + 8) * AQPAD + kb + tg + 4];
        }

        float l0 = 0.f, l1 = 0.f;
        float o[4][4];
#pragma unroll
        for (int nt = 0; nt < 4; nt++)
#pragma unroll
            for (int q = 0; q < 4; q++) o[nt][q] = 0.f;

        for (int kv = 0; kv < 8; kv++) {
            const int n0 = kv * 64;

            // ---- S = Q K^T (16x64 strip) ----
            float c[8][4];
#pragma unroll
            for (int nt = 0; nt < 8; nt++) {
                c[nt][0] = 0.f; c[nt][1] = 0.f; c[nt][2] = 0.f; c[nt][3] = 0.f;
            }
#pragma unroll
            for (int ks = 0; ks < 4; ks++) {
                const int kb = ks * 8;
#pragma unroll
                for (int nt = 0; nt < 8; nt++) {
                    int cc = n0 + nt * 8 + g;
                    unsigned b[2];
                    b[0] = Kt[(kb + tg) * KTPAD + cc];
                    b[1] = Kt[(kb + tg + 4) * KTPAD + cc];
                    mma_tf32(c[nt], aq[ks], b);
                }
            }

            // ---- masked exp (no max tracking), row sums ----
            unsigned w0a = smk[r0 * 16 + kv * 2], w0b = smk[r0 * 16 + kv * 2 + 1];
            unsigned w1a = smk[r1 * 16 + kv * 2], w1b = smk[r1 * 16 + kv * 2 + 1];
            float ts0 = 0.f, ts1 = 0.f;
#pragma unroll
            for (int nt = 0; nt < 8; nt++) {
                unsigned mw0 = (nt < 4) ? w0a : w0b;
                unsigned mw1 = (nt < 4) ? w1a : w1b;
                int sh = (nt & 3) * 8 + 2 * tg;
                float p00 = ((mw0 >> sh) & 1u)
                          ? __expf(fmaf(c[nt][0], 0.5f, -30.f)) : 0.f;
                float p01 = ((mw0 >> (sh + 1)) & 1u)
                          ? __expf(fmaf(c[nt][1], 0.5f, -30.f)) : 0.f;
                float p10 = ((mw1 >> sh) & 1u)
                          ? __expf(fmaf(c[nt][2], 0.5f, -30.f)) : 0.f;
                float p11 = ((mw1 >> (sh + 1)) & 1u)
                          ? __expf(fmaf(c[nt][3], 0.5f, -30.f)) : 0.f;
                c[nt][0] = p00; c[nt][1] = p01; c[nt][2] = p10; c[nt][3] = p11;
                ts0 += p00 + p01;  ts1 += p10 + p11;
            }
            ts0 += __shfl_xor_sync(0xffffffffu, ts0, 1);
            ts0 += __shfl_xor_sync(0xffffffffu, ts0, 2);
            ts1 += __shfl_xor_sync(0xffffffffu, ts1, 1);
            ts1 += __shfl_xor_sync(0xffffffffu, ts1, 2);
            l0 += ts0;
            l1 += ts1;

            // ---- O += P V : register shfl transpose -> A frags, then mma ----
#pragma unroll
            for (int ks = 0; ks < 8; ks++) {
                float v0, v1;
                unsigned a[4];
                v0 = __shfl_sync(0xffffffffu, c[ks][0], src);
                v1 = __shfl_sync(0xffffffffu, c[ks][1], src);
                a[0] = f2tf32(odd ? v1 : v0);
                v0 = __shfl_sync(0xffffffffu, c[ks][2], src);
                v1 = __shfl_sync(0xffffffffu, c[ks][3], src);
                a[1] = f2tf32(odd ? v1 : v0);
                v0 = __shfl_sync(0xffffffffu, c[ks][0], src2);
                v1 = __shfl_sync(0xffffffffu, c[ks][1], src2);
                a[2] = f2tf32(odd ? v1 : v0);
                v0 = __shfl_sync(0xffffffffu, c[ks][2], src2);
                v1 = __shfl_sync(0xffffffffu, c[ks][3], src2);
                a[3] = f2tf32(odd ? v1 : v0);
#pragma unroll
                for (int nt = 0; nt < 4; nt++) {
                    unsigned b[2];
                    b[0] = Vs[(n0 + ks * 8 + tg) * VSPAD + nt * 8 + g];
                    b[1] = Vs[(n0 + ks * 8 + tg + 4) * VSPAD + nt * 8 + g];
                    mma_tf32(o[nt], a, b);
                }
            }
        }

        // ---- epilogue: normalize, write ----
        float il0 = 1.f / l0, il1 = 1.f / l1;
#pragma unroll
        for (int nt = 0; nt < 4; nt++) {
            int col = cb + nt * 8 + 2 * tg;
            *(float2*)&g_aout[(rowbase + r0) * 128 + col] =
                make_float2(o[nt][0] * il0, o[nt][1] * il0);
            *(float2*)&g_aout[(rowbase + r1) * 128 + col] =
                make_float2(o[nt][2] * il1, o[nt][3] * il1);
        }
        __syncthreads();   // before next qt re-stages Asq
    }
}

// ---------------- final BN+ReLU into d_out -----------------------------------
__global__ void bn_apply_kernel(float* __restrict__ out)
{
    size_t i = (size_t)blockIdx.x * blockDim.x + threadIdx.x;
    if (i >= (size_t)ROWS * DCH) return;
    int ch = (int)(i & 127);
    out[i] = fmaxf(0.f, fmaf(g_oraw[i], g_scale[3 * 128 + ch], g_shift[3 * 128 + ch]));
}

// =============================================================================
extern "C" void kernel_launch(void* const* d_in, const int* in_sizes, int n_in,
                              void* d_out, int out_size)
{
    (void)in_sizes; (void)n_in; (void)out_size;
    const float* X     = (const float*)d_in[0];
    const float* STE   = (const float*)d_in[1];
    const float* A     = (const float*)d_in[2];
    const float* Wq    = (const float*)d_in[3];
    const float* gq    = (const float*)d_in[5];
    const float* betaq = (const float*)d_in[6];
    const float* Wk    = (const float*)d_in[7];
    const float* gk    = (const float*)d_in[9];
    const float* betak = (const float*)d_in[10];
    const float* Wv    = (const float*)d_in[11];
    const float* gv    = (const float*)d_in[13];
    const float* betav = (const float*)d_in[14];
    const float* Wo    = (const float*)d_in[15];
    const float* go    = (const float*)d_in[17];
    const float* betao = (const float*)d_in[18];
    float* out = (float*)d_out;

    void *pq, *pk, *pv, *pa, *po;
    cudaGetSymbolAddress(&pq, g_qraw);
    cudaGetSymbolAddress(&pk, g_kraw);
    cudaGetSymbolAddress(&pv, g_vraw);
    cudaGetSymbolAddress(&pa, g_aout);
    cudaGetSymbolAddress(&po, g_oraw);

    const int smem_attn = (32 * KTPAD + NNODES * VSPAD + 256 * AQPAD +
                           NNODES * 16) * (int)sizeof(unsigned);   // ~213 KB
    cudaFuncSetAttribute(attn_mma_kernel, cudaFuncAttributeMaxDynamicSharedMemorySize,
                         smem_attn);

    // 1) adjacency -> bitmap
    build_mask_kernel<<<16, 1024>>>(A);

    // 2) q/k/v projections (split-tf32, ~fp32 accurate, fused BN stats)
    mma_gemm_kernel<256, true><<<dim3(MBLK, 1, 3), 256>>>(
        X, STE, Wq, Wk, Wv, (float*)pq, (float*)pk, (float*)pv, 0);

    // 3) BN finalize for q/k/v
    bn_finalize_kernel<<<3, 512>>>(gq, betaq, gk, betak, gv, betav, 0);

    // 4) dense tensor-core masked attention (16 warps, no-max online softmax)
    attn_mma_kernel<<<dim3(NBT, NH), 512, smem_attn>>>();

    // 5) output projection (split-tf32, fused BN stats)
    mma_gemm_kernel<128, false><<<dim3(MBLK, 1, 1), 256>>>(
        (float*)pa, nullptr, Wo, Wo, Wo, (float*)po, (float*)po, (float*)po, 3);

    // 6) BN finalize for output
    bn_finalize_kernel<<<1, 512>>>(go, betao, go, betao, go, betao, 3);

    // 7) BN + ReLU -> d_out
    bn_apply_kernel<<<(ROWS * DCH + 255) / 256, 256>>>(out);
}

// round 8
// speedup vs baseline: 1.2154x; 1.2154x over previous
#include <cuda_runtime.h>
#include <cuda_bf16.h>
#include <math.h>

// Problem constants
#define ROWS   49152      // B*T*N = 8*12*512
#define DCH    128        // D
#define NNODES 512        // N
#define NBT    96         // B*T
#define NH     4          // heads (d)
#define MBLK   384        // ROWS / 128

// attention smem pads
#define KTPAD 520         // Kt row stride (unsigned), [32][520]
#define VSPAD 40          // Vs row stride, [512][40]  (8tg+g conflict-free)
#define AQPAD 36          // Asq row stride, [256][36]

// GEMM smem pads (bf16-pair words)
#define APAD 20           // A row stride in words (16 used): {20g+tg} distinct mod 32
#define BPAD 136          // B kpair stride in words: {8tg+g} distinct mod 32

// ---------------- scratch (device globals; no cudaMalloc allowed) ----------
__device__ float    g_qraw[ROWS * DCH];
__device__ float    g_kraw[ROWS * DCH];
__device__ float    g_vraw[ROWS * DCH];
__device__ float    g_aout[ROWS * DCH];
__device__ float    g_oraw[ROWS * DCH];
__device__ unsigned g_mask[NNODES * 16];      // A>0 bitmap: row n, 16 words
// deterministic BN partials: [z in 0..3][block 0..383][ch 0..127]
__device__ float g_psum[4 * MBLK * DCH];
__device__ float g_psumsq[4 * MBLK * DCH];
__device__ float g_scale[4 * DCH];
__device__ float g_shift[4 * DCH];

// ---------------- helpers ----------------------------------------------------
__device__ __forceinline__ unsigned f2tf32(float f) {
    unsigned r;
    asm("cvt.rna.tf32.f32 %0, %1;" : "=r"(r) : "f"(f));
    return r;
}

__device__ __forceinline__ void mma_tf32(float* c, const unsigned* a, const unsigned* b) {
    asm volatile(
        "mma.sync.aligned.m16n8k8.row.col.f32.tf32.tf32.f32 "
        "{%0,%1,%2,%3}, {%4,%5,%6,%7}, {%8,%9}, {%0,%1,%2,%3};\n"
        : "+f"(c[0]), "+f"(c[1]), "+f"(c[2]), "+f"(c[3])
        : "r"(a[0]), "r"(a[1]), "r"(a[2]), "r"(a[3]), "r"(b[0]), "r"(b[1]));
}

__device__ __forceinline__ void mma_bf16(float* c, const unsigned* a, const unsigned* b) {
    asm volatile(
        "mma.sync.aligned.m16n8k16.row.col.f32.bf16.bf16.f32 "
        "{%0,%1,%2,%3}, {%4,%5,%6,%7}, {%8,%9}, {%0,%1,%2,%3};\n"
        : "+f"(c[0]), "+f"(c[1]), "+f"(c[2]), "+f"(c[3])
        : "r"(a[0]), "r"(a[1]), "r"(a[2]), "r"(a[3]), "r"(b[0]), "r"(b[1]));
}

// split v into hi/lo bf16; return floats of the halves for packing
__device__ __forceinline__ void split_bf16(float v, unsigned short& h, unsigned short& l) {
    __nv_bfloat16 hb = __float2bfloat16_rn(v);
    float hf = __bfloat162float(hb);
    __nv_bfloat16 lb = __float2bfloat16_rn(v - hf);
    h = *(unsigned short*)&hb;
    l = *(unsigned short*)&lb;
}

__device__ __forceinline__ unsigned pack2(unsigned short lo, unsigned short hi) {
    return (unsigned)lo | ((unsigned)hi << 16);   // low 16 = even-k element
}

// ---------------- adjacency bitmap (warp per row, ballot) --------------------
__global__ void build_mask_kernel(const float* __restrict__ A)
{
    int row  = (blockIdx.x * blockDim.x + threadIdx.x) >> 5;
    int lane = threadIdx.x & 31;
    if (row >= NNODES) return;
    for (int w = 0; w < 16; w++) {
        float a = A[row * NNODES + w * 32 + lane];
        unsigned bal = __ballot_sync(0xffffffffu, a > 0.f);
        if (lane == 0) g_mask[row * 16 + w] = bal;
    }
}

// ---------------- split-bf16 tensor GEMM, 128x128 tile, BK=32 ---------------
// Y = A @ W via bf16x2 3-term scheme: Ah*Bh + Al*Bh + Ah*Bl (~fp32 accuracy,
// residual ~2^-16). Words hold adjacent-k bf16 pairs -> same LDS count as a
// single-pass tf32 k8 kernel, 1.5x the mma count. Bias dropped (cancels in
// BN). CAT: A=[X|STE], KDIM=256. Fused per-CTA BN sum/sumsq partials.
template <int KDIM, bool CAT>
__global__ __launch_bounds__(256)
void mma_gemm_kernel(const float* __restrict__ A0, const float* __restrict__ A1,
                     const float* __restrict__ W0, const float* __restrict__ W1,
                     const float* __restrict__ W2,
                     float* __restrict__ Y0, float* __restrict__ Y1,
                     float* __restrict__ Y2, int zbase)
{
    __shared__ unsigned AsH[128 * APAD], AsL[128 * APAD];   // [row][kpair]
    __shared__ unsigned BsH[16 * BPAD],  BsL[16 * BPAD];    // [kpair][n]
    __shared__ float ssum[2][128], ssq[2][128];

    const int z = blockIdx.z;
    const float* W = (z == 0) ? W0 : (z == 1) ? W1 : W2;
    float*       Y = (z == 0) ? Y0 : (z == 1) ? Y1 : Y2;

    const int tid  = threadIdx.x;
    const int lane = tid & 31;
    const int wid  = tid >> 5;
    const int wm   = wid >> 2;           // 0..1
    const int wn   = wid & 3;            // 0..3
    const int row0 = blockIdx.x * 128;
    const int g    = lane >> 2;
    const int tg   = lane & 3;

    float acc[4][4][4];
#pragma unroll
    for (int mt = 0; mt < 4; mt++)
#pragma unroll
        for (int nt = 0; nt < 4; nt++)
#pragma unroll
            for (int q = 0; q < 4; q++) acc[mt][nt][q] = 0.f;

    for (int k0 = 0; k0 < KDIM; k0 += 32) {
        const float* Abase;
        int kofs;
        if (CAT) {
            if (k0 < 128) { Abase = A0; kofs = k0; }
            else          { Abase = A1; kofs = k0 - 128; }
        } else { Abase = A0; kofs = k0; }

        // A tile: 128 rows x 32 k; thread handles a float4 (=2 pair-words)
#pragma unroll
        for (int t = 0; t < 4; t++) {
            int i  = tid + 256 * t;
            int r  = i >> 3;
            int kq = (i & 7) << 2;               // k offset 0..28
            float4 v = *(const float4*)(Abase + (size_t)(row0 + r) * 128 + kofs + kq);
            unsigned short hx, lx, hy, ly, hz, lz, hw, lw;
            split_bf16(v.x, hx, lx); split_bf16(v.y, hy, ly);
            split_bf16(v.z, hz, lz); split_bf16(v.w, hw, lw);
            int o = r * APAD + (kq >> 1);
            AsH[o + 0] = pack2(hx, hy);  AsH[o + 1] = pack2(hz, hw);
            AsL[o + 0] = pack2(lx, ly);  AsL[o + 1] = pack2(lz, lw);
        }
        // B tile: 32 k x 128 n; thread packs adjacent-k pairs for 4 columns
#pragma unroll
        for (int t = 0; t < 2; t++) {
            int i  = tid + 256 * t;
            int kp = i >> 5;                     // 0..15
            int n4 = (i & 31) << 2;
            float4 v0 = *(const float4*)(W + (size_t)(k0 + 2 * kp) * 128 + n4);
            float4 v1 = *(const float4*)(W + (size_t)(k0 + 2 * kp + 1) * 128 + n4);
            const float e0[4] = {v0.x, v0.y, v0.z, v0.w};
            const float e1[4] = {v1.x, v1.y, v1.z, v1.w};
            int o = kp * BPAD + n4;
#pragma unroll
            for (int e = 0; e < 4; e++) {
                unsigned short h0, l0, h1, l1;
                split_bf16(e0[e], h0, l0);
                split_bf16(e1[e], h1, l1);
                BsH[o + e] = pack2(h0, h1);      // low = even k
                BsL[o + e] = pack2(l0, l1);
            }
        }
        __syncthreads();

#pragma unroll
        for (int s = 0; s < 2; s++) {            // two k16 steps
            const int kb = s * 8;                // word base
            unsigned afH[4][4], afL[4][4];
#pragma unroll
            for (int mt = 0; mt < 4; mt++) {
                int rB = wm * 64 + mt * 16;
                afH[mt][0] = AsH[(rB + g) * APAD + kb + tg];
                afH[mt][1] = AsH[(rB + 8 + g) * APAD + kb + tg];
                afH[mt][2] = AsH[(rB + g) * APAD + kb + 4 + tg];
                afH[mt][3] = AsH[(rB + 8 + g) * APAD + kb + 4 + tg];
                afL[mt][0] = AsL[(rB + g) * APAD + kb + tg];
                afL[mt][1] = AsL[(rB + 8 + g) * APAD + kb + tg];
                afL[mt][2] = AsL[(rB + g) * APAD + kb + 4 + tg];
                afL[mt][3] = AsL[(rB + 8 + g) * APAD + kb + 4 + tg];
            }
#pragma unroll
            for (int nt = 0; nt < 4; nt++) {
                int cc = wn * 32 + nt * 8 + g;
                unsigned bfH[2], bfL[2];
                bfH[0] = BsH[(kb + tg) * BPAD + cc];
                bfH[1] = BsH[(kb + 4 + tg) * BPAD + cc];
                bfL[0] = BsL[(kb + tg) * BPAD + cc];
                bfL[1] = BsL[(kb + 4 + tg) * BPAD + cc];
#pragma unroll
                for (int mt = 0; mt < 4; mt++) {
                    mma_bf16(acc[mt][nt], afH[mt], bfH);
                    mma_bf16(acc[mt][nt], afL[mt], bfH);
                    mma_bf16(acc[mt][nt], afH[mt], bfL);
                }
            }
        }
        __syncthreads();
    }

    // -------- epilogue: store Y + fused per-CTA BN partial stats ------------
#pragma unroll
    for (int nt = 0; nt < 4; nt++) {
        float se = 0.f, so = 0.f, qe = 0.f, qo = 0.f;
#pragma unroll
        for (int mt = 0; mt < 4; mt++) {
            float c0 = acc[mt][nt][0], c1 = acc[mt][nt][1];
            float c2 = acc[mt][nt][2], c3 = acc[mt][nt][3];
            int r   = row0 + wm * 64 + mt * 16 + g;
            int col = wn * 32 + nt * 8 + tg * 2;
            *(float2*)(Y + (size_t)r * 128 + col)       = make_float2(c0, c1);
            *(float2*)(Y + (size_t)(r + 8) * 128 + col) = make_float2(c2, c3);
            se += c0 + c2;  so += c1 + c3;
            qe += c0 * c0 + c2 * c2;  qo += c1 * c1 + c3 * c3;
        }
#pragma unroll
        for (int o = 4; o < 32; o <<= 1) {
            se += __shfl_xor_sync(0xffffffffu, se, o);
            so += __shfl_xor_sync(0xffffffffu, so, o);
            qe += __shfl_xor_sync(0xffffffffu, qe, o);
            qo += __shfl_xor_sync(0xffffffffu, qo, o);
        }
        if (lane < 4) {
            int col = wn * 32 + nt * 8 + lane * 2;
            ssum[wm][col]     = se;  ssum[wm][col + 1] = so;
            ssq[wm][col]      = qe;  ssq[wm][col + 1]  = qo;
        }
    }
    __syncthreads();
    if (tid < 128) {
        int slot = ((zbase + z) * MBLK + blockIdx.x) * DCH + tid;
        g_psum[slot]   = ssum[0][tid] + ssum[1][tid];
        g_psumsq[slot] = ssq[0][tid] + ssq[1][tid];
    }
}

// ---------------- BN finalize: reduce 384 partials (parallel) ---------------
__global__ void bn_finalize_kernel(const float* __restrict__ g0, const float* __restrict__ be0,
                                   const float* __restrict__ g1, const float* __restrict__ be1,
                                   const float* __restrict__ g2, const float* __restrict__ be2,
                                   int zbase)
{
    __shared__ float ss[512], sq[512];
    int z = blockIdx.x;
    const float* g  = (z == 0) ? g0 : (z == 1) ? g1 : g2;
    const float* be = (z == 0) ? be0 : (z == 1) ? be1 : be2;
    int ch = threadIdx.x & 127, part = threadIdx.x >> 7;
    float s = 0.f, s2 = 0.f;
    for (int b = part; b < MBLK; b += 4) {
        int slot = ((zbase + z) * MBLK + b) * DCH + ch;
        s  += g_psum[slot];
        s2 += g_psumsq[slot];
    }
    ss[threadIdx.x] = s;  sq[threadIdx.x] = s2;
    __syncthreads();
    if (threadIdx.x < 128) {
        s  = ss[ch] + ss[ch + 128] + ss[ch + 256] + ss[ch + 384];
        s2 = sq[ch] + sq[ch + 128] + sq[ch + 256] + sq[ch + 384];
        const float inv_cnt = 1.f / (float)ROWS;
        float mu  = s * inv_cnt;
        float var = s2 * inv_cnt - mu * mu;
        float sc  = g[ch] * rsqrtf(var + 1e-5f);
        g_scale[(zbase + z) * 128 + ch] = sc;
        g_shift[(zbase + z) * 128 + ch] = be[ch] - mu * sc;
    }
}

// ---------------- dense tensor-core masked flash-attention v3 ---------------
// (unchanged from R7: 512 threads, hoisted Q frags, no-max softmax, register
// shfl transpose for P; measured 178 us)
__global__ __launch_bounds__(512)
void attn_mma_kernel()
{
    extern __shared__ unsigned smu[];
    unsigned* Kt  = smu;                          // [32][KTPAD]  K^T tf32
    unsigned* Vs  = Kt  + 32 * KTPAD;             // [512][VSPAD] V tf32
    unsigned* Asq = Vs  + NNODES * VSPAD;         // [256][AQPAD] Q tile tf32
    unsigned* smk = Asq + 256 * AQPAD;            // [512][16] mask bitmap

    const int bt   = blockIdx.x;
    const int h    = blockIdx.y;
    const int tid  = threadIdx.x;
    const int lane = tid & 31;
    const int wid  = tid >> 5;                    // 0..15
    const int g    = lane >> 2;
    const int tg   = lane & 3;
    const size_t rowbase = (size_t)bt * NNODES;
    const int cb = h * 32;

    const float scq = g_scale[0 * 128 + cb + lane], shq = g_shift[0 * 128 + cb + lane];
    const float sck = g_scale[1 * 128 + cb + lane], shk = g_shift[1 * 128 + cb + lane];
    const float scv = g_scale[2 * 128 + cb + lane], shv = g_shift[2 * 128 + cb + lane];

    for (int idx = tid; idx < NNODES * 32; idx += 512) {
        int n = idx >> 5;                         // (idx & 31) == lane
        float kv = g_kraw[(rowbase + n) * 128 + cb + lane];
        Kt[lane * KTPAD + n] = f2tf32(fmaxf(0.f, fmaf(kv, sck, shk)));
        float vv = g_vraw[(rowbase + n) * 128 + cb + lane];
        Vs[n * VSPAD + lane] = f2tf32(fmaxf(0.f, fmaf(vv, scv, shv)));
    }
    for (int idx = tid; idx < NNODES * 16; idx += 512) smk[idx] = g_mask[idx];
    __syncthreads();

    const int q0 = wid * 16;
    const int src  = 4 * g + (tg >> 1);
    const int src2 = src + 2;
    const bool odd = (tg & 1);

    for (int qt = 0; qt < 2; qt++) {
        for (int idx = tid; idx < 256 * 32; idx += 512) {
            int r = idx >> 5;
            float qv = g_qraw[(rowbase + qt * 256 + r) * 128 + cb + lane];
            Asq[r * AQPAD + lane] = f2tf32(fmaxf(0.f, fmaf(qv, scq, shq)));
        }
        __syncthreads();

        const int r0 = qt * 256 + q0 + g;
        const int r1 = r0 + 8;

        unsigned aq[4][4];
#pragma unroll
        for (int ks = 0; ks < 4; ks++) {
            const int kb = ks * 8;
            aq[ks][0] = Asq[(q0 + g) * AQPAD + kb + tg];
            aq[ks][1] = Asq[(q0 + g + 8) * AQPAD + kb + tg];
            aq[ks][2] = Asq[(q0 + g) * AQPAD + kb + tg + 4];
            aq[ks][3] = Asq[(q0 + g + 8) * AQPAD + kb + tg + 4];
        }

        float l0 = 0.f, l1 = 0.f;
        float o[4][4];
#pragma unroll
        for (int nt = 0; nt < 4; nt++)
#pragma unroll
            for (int q = 0; q < 4; q++) o[nt][q] = 0.f;

        for (int kv = 0; kv < 8; kv++) {
            const int n0 = kv * 64;

            float c[8][4];
#pragma unroll
            for (int nt = 0; nt < 8; nt++) {
                c[nt][0] = 0.f; c[nt][1] = 0.f; c[nt][2] = 0.f; c[nt][3] = 0.f;
            }
#pragma unroll
            for (int ks = 0; ks < 4; ks++) {
                const int kb = ks * 8;
#pragma unroll
                for (int nt = 0; nt < 8; nt++) {
                    int cc = n0 + nt * 8 + g;
                    unsigned b[2];
                    b[0] = Kt[(kb + tg) * KTPAD + cc];
                    b[1] = Kt[(kb + tg + 4) * KTPAD + cc];
                    mma_tf32(c[nt], aq[ks], b);
                }
            }

            unsigned w0a = smk[r0 * 16 + kv * 2], w0b = smk[r0 * 16 + kv * 2 + 1];
            unsigned w1a = smk[r1 * 16 + kv * 2], w1b = smk[r1 * 16 + kv * 2 + 1];
            float ts0 = 0.f, ts1 = 0.f;
#pragma unroll
            for (int nt = 0; nt < 8; nt++) {
                unsigned mw0 = (nt < 4) ? w0a : w0b;
                unsigned mw1 = (nt < 4) ? w1a : w1b;
                int sh = (nt & 3) * 8 + 2 * tg;
                float p00 = ((mw0 >> sh) & 1u)
                          ? __expf(fmaf(c[nt][0], 0.5f, -30.f)) : 0.f;
                float p01 = ((mw0 >> (sh + 1)) & 1u)
                          ? __expf(fmaf(c[nt][1], 0.5f, -30.f)) : 0.f;
                float p10 = ((mw1 >> sh) & 1u)
                          ? __expf(fmaf(c[nt][2], 0.5f, -30.f)) : 0.f;
                float p11 = ((mw1 >> (sh + 1)) & 1u)
                          ? __expf(fmaf(c[nt][3], 0.5f, -30.f)) : 0.f;
                c[nt][0] = p00; c[nt][1] = p01; c[nt][2] = p10; c[nt][3] = p11;
                ts0 += p00 + p01;  ts1 += p10 + p11;
            }
            ts0 += __shfl_xor_sync(0xffffffffu, ts0, 1);
            ts0 += __shfl_xor_sync(0xffffffffu, ts0, 2);
            ts1 += __shfl_xor_sync(0xffffffffu, ts1, 1);
            ts1 += __shfl_xor_sync(0xffffffffu, ts1, 2);
            l0 += ts0;
            l1 += ts1;

#pragma unroll
            for (int ks = 0; ks < 8; ks++) {
                float v0, v1;
                unsigned a[4];
                v0 = __shfl_sync(0xffffffffu, c[ks][0], src);
                v1 = __shfl_sync(0xffffffffu, c[ks][1], src);
                a[0] = f2tf32(odd ? v1 : v0);
                v0 = __shfl_sync(0xffffffffu, c[ks][2], src);
                v1 = __shfl_sync(0xffffffffu, c[ks][3], src);
                a[1] = f2tf32(odd ? v1 : v0);
                v0 = __shfl_sync(0xffffffffu, c[ks][0], src2);
                v1 = __shfl_sync(0xffffffffu, c[ks][1], src2);
                a[2] = f2tf32(odd ? v1 : v0);
                v0 = __shfl_sync(0xffffffffu, c[ks][2], src2);
                v1 = __shfl_sync(0xffffffffu, c[ks][3], src2);
                a[3] = f2tf32(odd ? v1 : v0);
#pragma unroll
                for (int nt = 0; nt < 4; nt++) {
                    unsigned b[2];
                    b[0] = Vs[(n0 + ks * 8 + tg) * VSPAD + nt * 8 + g];
                    b[1] = Vs[(n0 + ks * 8 + tg + 4) * VSPAD + nt * 8 + g];
                    mma_tf32(o[nt], a, b);
                }
            }
        }

        float il0 = 1.f / l0, il1 = 1.f / l1;
#pragma unroll
        for (int nt = 0; nt < 4; nt++) {
            int col = cb + nt * 8 + 2 * tg;
            *(float2*)&g_aout[(rowbase + r0) * 128 + col] =
                make_float2(o[nt][0] * il0, o[nt][1] * il0);
            *(float2*)&g_aout[(rowbase + r1) * 128 + col] =
                make_float2(o[nt][2] * il1, o[nt][3] * il1);
        }
        __syncthreads();
    }
}

// ---------------- final BN+ReLU into d_out -----------------------------------
__global__ void bn_apply_kernel(float* __restrict__ out)
{
    size_t i = (size_t)blockIdx.x * blockDim.x + threadIdx.x;
    if (i >= (size_t)ROWS * DCH) return;
    int ch = (int)(i & 127);
    out[i] = fmaxf(0.f, fmaf(g_oraw[i], g_scale[3 * 128 + ch], g_shift[3 * 128 + ch]));
}

// =============================================================================
extern "C" void kernel_launch(void* const* d_in, const int* in_sizes, int n_in,
                              void* d_out, int out_size)
{
    (void)in_sizes; (void)n_in; (void)out_size;
    const float* X     = (const float*)d_in[0];
    const float* STE   = (const float*)d_in[1];
    const float* A     = (const float*)d_in[2];
    const float* Wq    = (const float*)d_in[3];
    const float* gq    = (const float*)d_in[5];
    const float* betaq = (const float*)d_in[6];
    const float* Wk    = (const float*)d_in[7];
    const float* gk    = (const float*)d_in[9];
    const float* betak = (const float*)d_in[10];
    const float* Wv    = (const float*)d_in[11];
    const float* gv    = (const float*)d_in[13];
    const float* betav = (const float*)d_in[14];
    const float* Wo    = (const float*)d_in[15];
    const float* go    = (const float*)d_in[17];
    const float* betao = (const float*)d_in[18];
    float* out = (float*)d_out;

    void *pq, *pk, *pv, *pa, *po;
    cudaGetSymbolAddress(&pq, g_qraw);
    cudaGetSymbolAddress(&pk, g_kraw);
    cudaGetSymbolAddress(&pv, g_vraw);
    cudaGetSymbolAddress(&pa, g_aout);
    cudaGetSymbolAddress(&po, g_oraw);

    const int smem_attn = (32 * KTPAD + NNODES * VSPAD + 256 * AQPAD +
                           NNODES * 16) * (int)sizeof(unsigned);   // ~213 KB
    cudaFuncSetAttribute(attn_mma_kernel, cudaFuncAttributeMaxDynamicSharedMemorySize,
                         smem_attn);

    // 1) adjacency -> bitmap
    build_mask_kernel<<<16, 1024>>>(A);

    // 2) q/k/v projections (split-bf16 3-term, ~fp32 accurate, fused BN stats)
    mma_gemm_kernel<256, true><<<dim3(MBLK, 1, 3), 256>>>(
        X, STE, Wq, Wk, Wv, (float*)pq, (float*)pk, (float*)pv, 0);

    // 3) BN finalize for q/k/v
    bn_finalize_kernel<<<3, 512>>>(gq, betaq, gk, betak, gv, betav, 0);

    // 4) dense tensor-core masked attention (16 warps, no-max online softmax)
    attn_mma_kernel<<<dim3(NBT, NH), 512, smem_attn>>>();

    // 5) output projection (split-bf16 3-term, fused BN stats)
    mma_gemm_kernel<128, false><<<dim3(MBLK, 1, 1), 256>>>(
        (float*)pa, nullptr, Wo, Wo, Wo, (float*)po, (float*)po, (float*)po, 3);

    // 6) BN finalize for output
    bn_finalize_kernel<<<1, 512>>>(go, betao, go, betao, go, betao, 3);

    // 7) BN + ReLU -> d_out
    bn_apply_kernel<<<(ROWS * DCH + 255) / 256, 256>>>(out);
}

// round 9
// speedup vs baseline: 1.2650x; 1.0408x over previous
#include <cuda_runtime.h>
#include <cuda_bf16.h>
#include <math.h>

// Problem constants
#define ROWS   49152      // B*T*N = 8*12*512
#define DCH    128        // D
#define NNODES 512        // N
#define NBT    96         // B*T
#define NH     4          // heads (d)
#define MBLK   384        // ROWS / 128

// attention smem strides (units: 4B words)
#define KT2PAD 1032       // Ktp row stride: [16][1032], mod32=8 -> conflict-free LDS.64
#define VPPAD  72         // Vp row stride:  [256][72],  mod32=8 -> conflict-free LDS.64
#define AQPAD  36         // Asq row stride, [256][36]

// GEMM smem pads (bf16-pair words)
#define APAD 20           // A row stride in words (16 used)
#define BPAD 136          // B kpair stride in words

// ---------------- scratch (device globals; no cudaMalloc allowed) ----------
__device__ float    g_qraw[ROWS * DCH];
__device__ float    g_kraw[ROWS * DCH];
__device__ float    g_vraw[ROWS * DCH];
__device__ float    g_aout[ROWS * DCH];
__device__ float    g_oraw[ROWS * DCH];
__device__ unsigned g_mask[NNODES * 16];      // A>0 bitmap: row n, 16 words
// deterministic BN partials: [z in 0..3][block 0..383][ch 0..127]
__device__ float g_psum[4 * MBLK * DCH];
__device__ float g_psumsq[4 * MBLK * DCH];
__device__ float g_scale[4 * DCH];
__device__ float g_shift[4 * DCH];

// ---------------- helpers ----------------------------------------------------
__device__ __forceinline__ unsigned f2tf32(float f) {
    unsigned r;
    asm("cvt.rna.tf32.f32 %0, %1;" : "=r"(r) : "f"(f));
    return r;
}

__device__ __forceinline__ void mma_tf32(float* c, const unsigned* a, const unsigned* b) {
    asm volatile(
        "mma.sync.aligned.m16n8k8.row.col.f32.tf32.tf32.f32 "
        "{%0,%1,%2,%3}, {%4,%5,%6,%7}, {%8,%9}, {%0,%1,%2,%3};\n"
        : "+f"(c[0]), "+f"(c[1]), "+f"(c[2]), "+f"(c[3])
        : "r"(a[0]), "r"(a[1]), "r"(a[2]), "r"(a[3]), "r"(b[0]), "r"(b[1]));
}

__device__ __forceinline__ void mma_bf16(float* c, const unsigned* a, const unsigned* b) {
    asm volatile(
        "mma.sync.aligned.m16n8k16.row.col.f32.bf16.bf16.f32 "
        "{%0,%1,%2,%3}, {%4,%5,%6,%7}, {%8,%9}, {%0,%1,%2,%3};\n"
        : "+f"(c[0]), "+f"(c[1]), "+f"(c[2]), "+f"(c[3])
        : "r"(a[0]), "r"(a[1]), "r"(a[2]), "r"(a[3]), "r"(b[0]), "r"(b[1]));
}

__device__ __forceinline__ void split_bf16(float v, unsigned short& h, unsigned short& l) {
    __nv_bfloat16 hb = __float2bfloat16_rn(v);
    float hf = __bfloat162float(hb);
    __nv_bfloat16 lb = __float2bfloat16_rn(v - hf);
    h = *(unsigned short*)&hb;
    l = *(unsigned short*)&lb;
}

__device__ __forceinline__ unsigned pack2(unsigned short lo, unsigned short hi) {
    return (unsigned)lo | ((unsigned)hi << 16);   // low 16 = even-k element
}

// ---------------- adjacency bitmap (warp per row, ballot) --------------------
__global__ void build_mask_kernel(const float* __restrict__ A)
{
    int row  = (blockIdx.x * blockDim.x + threadIdx.x) >> 5;
    int lane = threadIdx.x & 31;
    if (row >= NNODES) return;
    for (int w = 0; w < 16; w++) {
        float a = A[row * NNODES + w * 32 + lane];
        unsigned bal = __ballot_sync(0xffffffffu, a > 0.f);
        if (lane == 0) g_mask[row * 16 + w] = bal;
    }
}

// ---------------- split-bf16 tensor GEMM, 128x128 tile, BK=32 ---------------
// (unchanged from R8: AhBh + AlBh + AhBl, ~fp32 accuracy; fused BN partials)
template <int KDIM, bool CAT>
__global__ __launch_bounds__(256)
void mma_gemm_kernel(const float* __restrict__ A0, const float* __restrict__ A1,
                     const float* __restrict__ W0, const float* __restrict__ W1,
                     const float* __restrict__ W2,
                     float* __restrict__ Y0, float* __restrict__ Y1,
                     float* __restrict__ Y2, int zbase)
{
    __shared__ unsigned AsH[128 * APAD], AsL[128 * APAD];   // [row][kpair]
    __shared__ unsigned BsH[16 * BPAD],  BsL[16 * BPAD];    // [kpair][n]
    __shared__ float ssum[2][128], ssq[2][128];

    const int z = blockIdx.z;
    const float* W = (z == 0) ? W0 : (z == 1) ? W1 : W2;
    float*       Y = (z == 0) ? Y0 : (z == 1) ? Y1 : Y2;

    const int tid  = threadIdx.x;
    const int lane = tid & 31;
    const int wid  = tid >> 5;
    const int wm   = wid >> 2;
    const int wn   = wid & 3;
    const int row0 = blockIdx.x * 128;
    const int g    = lane >> 2;
    const int tg   = lane & 3;

    float acc[4][4][4];
#pragma unroll
    for (int mt = 0; mt < 4; mt++)
#pragma unroll
        for (int nt = 0; nt < 4; nt++)
#pragma unroll
            for (int q = 0; q < 4; q++) acc[mt][nt][q] = 0.f;

    for (int k0 = 0; k0 < KDIM; k0 += 32) {
        const float* Abase;
        int kofs;
        if (CAT) {
            if (k0 < 128) { Abase = A0; kofs = k0; }
            else          { Abase = A1; kofs = k0 - 128; }
        } else { Abase = A0; kofs = k0; }

#pragma unroll
        for (int t = 0; t < 4; t++) {
            int i  = tid + 256 * t;
            int r  = i >> 3;
            int kq = (i & 7) << 2;
            float4 v = *(const float4*)(Abase + (size_t)(row0 + r) * 128 + kofs + kq);
            unsigned short hx, lx, hy, ly, hz, lz, hw, lw;
            split_bf16(v.x, hx, lx); split_bf16(v.y, hy, ly);
            split_bf16(v.z, hz, lz); split_bf16(v.w, hw, lw);
            int o = r * APAD + (kq >> 1);
            AsH[o + 0] = pack2(hx, hy);  AsH[o + 1] = pack2(hz, hw);
            AsL[o + 0] = pack2(lx, ly);  AsL[o + 1] = pack2(lz, lw);
        }
#pragma unroll
        for (int t = 0; t < 2; t++) {
            int i  = tid + 256 * t;
            int kp = i >> 5;
            int n4 = (i & 31) << 2;
            float4 v0 = *(const float4*)(W + (size_t)(k0 + 2 * kp) * 128 + n4);
            float4 v1 = *(const float4*)(W + (size_t)(k0 + 2 * kp + 1) * 128 + n4);
            const float e0[4] = {v0.x, v0.y, v0.z, v0.w};
            const float e1[4] = {v1.x, v1.y, v1.z, v1.w};
            int o = kp * BPAD + n4;
#pragma unroll
            for (int e = 0; e < 4; e++) {
                unsigned short h0, l0, h1, l1;
                split_bf16(e0[e], h0, l0);
                split_bf16(e1[e], h1, l1);
                BsH[o + e] = pack2(h0, h1);
                BsL[o + e] = pack2(l0, l1);
            }
        }
        __syncthreads();

#pragma unroll
        for (int s = 0; s < 2; s++) {
            const int kb = s * 8;
            unsigned afH[4][4], afL[4][4];
#pragma unroll
            for (int mt = 0; mt < 4; mt++) {
                int rB = wm * 64 + mt * 16;
                afH[mt][0] = AsH[(rB + g) * APAD + kb + tg];
                afH[mt][1] = AsH[(rB + 8 + g) * APAD + kb + tg];
                afH[mt][2] = AsH[(rB + g) * APAD + kb + 4 + tg];
                afH[mt][3] = AsH[(rB + 8 + g) * APAD + kb + 4 + tg];
                afL[mt][0] = AsL[(rB + g) * APAD + kb + tg];
                afL[mt][1] = AsL[(rB + 8 + g) * APAD + kb + tg];
                afL[mt][2] = AsL[(rB + g) * APAD + kb + 4 + tg];
                afL[mt][3] = AsL[(rB + 8 + g) * APAD + kb + 4 + tg];
            }
#pragma unroll
            for (int nt = 0; nt < 4; nt++) {
                int cc = wn * 32 + nt * 8 + g;
                unsigned bfH[2], bfL[2];
                bfH[0] = BsH[(kb + tg) * BPAD + cc];
                bfH[1] = BsH[(kb + 4 + tg) * BPAD + cc];
                bfL[0] = BsL[(kb + tg) * BPAD + cc];
                bfL[1] = BsL[(kb + 4 + tg) * BPAD + cc];
#pragma unroll
                for (int mt = 0; mt < 4; mt++) {
                    mma_bf16(acc[mt][nt], afH[mt], bfH);
                    mma_bf16(acc[mt][nt], afL[mt], bfH);
                    mma_bf16(acc[mt][nt], afH[mt], bfL);
                }
            }
        }
        __syncthreads();
    }

#pragma unroll
    for (int nt = 0; nt < 4; nt++) {
        float se = 0.f, so = 0.f, qe = 0.f, qo = 0.f;
#pragma unroll
        for (int mt = 0; mt < 4; mt++) {
            float c0 = acc[mt][nt][0], c1 = acc[mt][nt][1];
            float c2 = acc[mt][nt][2], c3 = acc[mt][nt][3];
            int r   = row0 + wm * 64 + mt * 16 + g;
            int col = wn * 32 + nt * 8 + tg * 2;
            *(float2*)(Y + (size_t)r * 128 + col)       = make_float2(c0, c1);
            *(float2*)(Y + (size_t)(r + 8) * 128 + col) = make_float2(c2, c3);
            se += c0 + c2;  so += c1 + c3;
            qe += c0 * c0 + c2 * c2;  qo += c1 * c1 + c3 * c3;
        }
#pragma unroll
        for (int o = 4; o < 32; o <<= 1) {
            se += __shfl_xor_sync(0xffffffffu, se, o);
            so += __shfl_xor_sync(0xffffffffu, so, o);
            qe += __shfl_xor_sync(0xffffffffu, qe, o);
            qo += __shfl_xor_sync(0xffffffffu, qo, o);
        }
        if (lane < 4) {
            int col = wn * 32 + nt * 8 + lane * 2;
            ssum[wm][col]     = se;  ssum[wm][col + 1] = so;
            ssq[wm][col]      = qe;  ssq[wm][col + 1]  = qo;
        }
    }
    __syncthreads();
    if (tid < 128) {
        int slot = ((zbase + z) * MBLK + blockIdx.x) * DCH + tid;
        g_psum[slot]   = ssum[0][tid] + ssum[1][tid];
        g_psumsq[slot] = ssq[0][tid] + ssq[1][tid];
    }
}

// ---------------- BN finalize: reduce 384 partials (parallel) ---------------
__global__ void bn_finalize_kernel(const float* __restrict__ g0, const float* __restrict__ be0,
                                   const float* __restrict__ g1, const float* __restrict__ be1,
                                   const float* __restrict__ g2, const float* __restrict__ be2,
                                   int zbase)
{
    __shared__ float ss[512], sq[512];
    int z = blockIdx.x;
    const float* g  = (z == 0) ? g0 : (z == 1) ? g1 : g2;
    const float* be = (z == 0) ? be0 : (z == 1) ? be1 : be2;
    int ch = threadIdx.x & 127, part = threadIdx.x >> 7;
    float s = 0.f, s2 = 0.f;
    for (int b = part; b < MBLK; b += 4) {
        int slot = ((zbase + z) * MBLK + b) * DCH + ch;
        s  += g_psum[slot];
        s2 += g_psumsq[slot];
    }
    ss[threadIdx.x] = s;  sq[threadIdx.x] = s2;
    __syncthreads();
    if (threadIdx.x < 128) {
        s  = ss[ch] + ss[ch + 128] + ss[ch + 256] + ss[ch + 384];
        s2 = sq[ch] + sq[ch + 128] + sq[ch + 256] + sq[ch + 384];
        const float inv_cnt = 1.f / (float)ROWS;
        float mu  = s * inv_cnt;
        float var = s2 * inv_cnt - mu * mu;
        float sc  = g[ch] * rsqrtf(var + 1e-5f);
        g_scale[(zbase + z) * 128 + ch] = sc;
        g_shift[(zbase + z) * 128 + ch] = be[ch] - mu * sc;
    }
}

// ---------------- dense tensor-core masked flash-attention v4 ---------------
// 512 threads, 16 warps, warp owns 16 q rows of a 256-row super-tile.
// kv strips of 32 (c[4][4] live -> no spills). Paired smem layouts:
//   Ktp[(ks*4+tg)][2n+half]  : QK B-frag = one LDS.64 (rows ch, ch+4)
//   Vp[(blk*4+tg)][2ch+half] : PV B-frag = one LDS.64 (nodes m, m+4)
// Same numerics as R8 (tf32, no-max softmax exp(s/2-30), bitmap mask).
__global__ __launch_bounds__(512)
void attn_mma_kernel()
{
    extern __shared__ unsigned smu[];
    unsigned* Ktp = smu;                          // [16][KT2PAD]
    unsigned* Vp  = Ktp + 16 * KT2PAD;            // [256][VPPAD]
    unsigned* Asq = Vp  + 256 * VPPAD;            // [256][AQPAD]
    unsigned* smk = Asq + 256 * AQPAD;            // [512][16]

    const int bt   = blockIdx.x;
    const int h    = blockIdx.y;
    const int tid  = threadIdx.x;
    const int lane = tid & 31;
    const int wid  = tid >> 5;                    // 0..15
    const int g    = lane >> 2;
    const int tg   = lane & 3;
    const size_t rowbase = (size_t)bt * NNODES;
    const int cb = h * 32;

    const float scq = g_scale[0 * 128 + cb + lane], shq = g_shift[0 * 128 + cb + lane];
    const float sck = g_scale[1 * 128 + cb + lane], shk = g_shift[1 * 128 + cb + lane];
    const float scv = g_scale[2 * 128 + cb + lane], shv = g_shift[2 * 128 + cb + lane];

    // stage K -> Ktp (channel-paired) and V -> Vp (node-paired), BN+ReLU fused
    {
        const int c     = lane;
        const int krow  = (c >> 3) * 4 + (c & 3);
        const int khalf = (c & 7) >> 2;
        for (int idx = tid; idx < NNODES * 32; idx += 512) {
            int n = idx >> 5;                     // (idx & 31) == lane
            float kv = g_kraw[(rowbase + n) * 128 + cb + c];
            Ktp[krow * KT2PAD + 2 * n + khalf] =
                f2tf32(fmaxf(0.f, fmaf(kv, sck, shk)));
            float vv = g_vraw[(rowbase + n) * 128 + cb + c];
            int vrow  = (n >> 3) * 4 + (n & 3);
            int vhalf = (n & 7) >> 2;
            Vp[vrow * VPPAD + 2 * c + vhalf] =
                f2tf32(fmaxf(0.f, fmaf(vv, scv, shv)));
        }
    }
    for (int idx = tid; idx < NNODES * 16; idx += 512) smk[idx] = g_mask[idx];
    __syncthreads();

    const int q0 = wid * 16;
    const int src  = 4 * g + (tg >> 1);
    const int src2 = src + 2;
    const bool odd = (tg & 1);

    for (int qt = 0; qt < 2; qt++) {
        for (int idx = tid; idx < 256 * 32; idx += 512) {
            int r = idx >> 5;
            float qv = g_qraw[(rowbase + qt * 256 + r) * 128 + cb + lane];
            Asq[r * AQPAD + lane] = f2tf32(fmaxf(0.f, fmaf(qv, scq, shq)));
        }
        __syncthreads();

        const int r0 = qt * 256 + q0 + g;
        const int r1 = r0 + 8;

        // hoist Q fragments (invariant across kv strips)
        unsigned aq[4][4];
#pragma unroll
        for (int ks = 0; ks < 4; ks++) {
            const int kb = ks * 8;
            aq[ks][0] = Asq[(q0 + g) * AQPAD + kb + tg];
            aq[ks][1] = Asq[(q0 + g + 8) * AQPAD + kb + tg];
            aq[ks][2] = Asq[(q0 + g) * AQPAD + kb + tg + 4];
            aq[ks][3] = Asq[(q0 + g + 8) * AQPAD + kb + tg + 4];
        }

        float l0 = 0.f, l1 = 0.f;
        float o[4][4];
#pragma unroll
        for (int nt = 0; nt < 4; nt++)
#pragma unroll
            for (int q = 0; q < 4; q++) o[nt][q] = 0.f;

        for (int kv = 0; kv < 16; kv++) {
            const int n0 = kv * 32;

            // ---- S = Q K^T (16x32 strip), paired LDS.64 B-frags ----
            float c[4][4];
#pragma unroll
            for (int nt = 0; nt < 4; nt++) {
                c[nt][0] = 0.f; c[nt][1] = 0.f; c[nt][2] = 0.f; c[nt][3] = 0.f;
            }
#pragma unroll
            for (int ks = 0; ks < 4; ks++) {
#pragma unroll
                for (int nt = 0; nt < 4; nt++) {
                    int cc = n0 + nt * 8 + g;
                    uint2 b2 = *(const uint2*)&Ktp[(ks * 4 + tg) * KT2PAD + 2 * cc];
                    unsigned b[2] = {b2.x, b2.y};
                    mma_tf32(c[nt], aq[ks], b);
                }
            }

            // ---- masked exp (no max tracking), strip sums ----
            unsigned w0 = smk[r0 * 16 + kv];
            unsigned w1 = smk[r1 * 16 + kv];
            float ts0 = 0.f, ts1 = 0.f;
#pragma unroll
            for (int nt = 0; nt < 4; nt++) {
                int sh = nt * 8 + 2 * tg;
                float p00 = ((w0 >> sh) & 1u)
                          ? __expf(fmaf(c[nt][0], 0.5f, -30.f)) : 0.f;
                float p01 = ((w0 >> (sh + 1)) & 1u)
                          ? __expf(fmaf(c[nt][1], 0.5f, -30.f)) : 0.f;
                float p10 = ((w1 >> sh) & 1u)
                          ? __expf(fmaf(c[nt][2], 0.5f, -30.f)) : 0.f;
                float p11 = ((w1 >> (sh + 1)) & 1u)
                          ? __expf(fmaf(c[nt][3], 0.5f, -30.f)) : 0.f;
                c[nt][0] = p00; c[nt][1] = p01; c[nt][2] = p10; c[nt][3] = p11;
                ts0 += p00 + p01;  ts1 += p10 + p11;
            }
            ts0 += __shfl_xor_sync(0xffffffffu, ts0, 1);
            ts0 += __shfl_xor_sync(0xffffffffu, ts0, 2);
            ts1 += __shfl_xor_sync(0xffffffffu, ts1, 1);
            ts1 += __shfl_xor_sync(0xffffffffu, ts1, 2);
            l0 += ts0;
            l1 += ts1;

            // ---- O += P V : shfl transpose -> A frags; paired LDS.64 B ----
#pragma unroll
            for (int ks = 0; ks < 4; ks++) {
                float v0, v1;
                unsigned a[4];
                v0 = __shfl_sync(0xffffffffu, c[ks][0], src);
                v1 = __shfl_sync(0xffffffffu, c[ks][1], src);
                a[0] = f2tf32(odd ? v1 : v0);
                v0 = __shfl_sync(0xffffffffu, c[ks][2], src);
                v1 = __shfl_sync(0xffffffffu, c[ks][3], src);
                a[1] = f2tf32(odd ? v1 : v0);
                v0 = __shfl_sync(0xffffffffu, c[ks][0], src2);
                v1 = __shfl_sync(0xffffffffu, c[ks][1], src2);
                a[2] = f2tf32(odd ? v1 : v0);
                v0 = __shfl_sync(0xffffffffu, c[ks][2], src2);
                v1 = __shfl_sync(0xffffffffu, c[ks][3], src2);
                a[3] = f2tf32(odd ? v1 : v0);
                const int blk = kv * 4 + ks;
#pragma unroll
                for (int nt = 0; nt < 4; nt++) {
                    uint2 b2 = *(const uint2*)&Vp[(blk * 4 + tg) * VPPAD
                                                  + 2 * (nt * 8 + g)];
                    unsigned b[2] = {b2.x, b2.y};
                    mma_tf32(o[nt], a, b);
                }
            }
        }

        // ---- epilogue: normalize, write ----
        float il0 = 1.f / l0, il1 = 1.f / l1;
#pragma unroll
        for (int nt = 0; nt < 4; nt++) {
            int col = cb + nt * 8 + 2 * tg;
            *(float2*)&g_aout[(rowbase + r0) * 128 + col] =
                make_float2(o[nt][0] * il0, o[nt][1] * il0);
            *(float2*)&g_aout[(rowbase + r1) * 128 + col] =
                make_float2(o[nt][2] * il1, o[nt][3] * il1);
        }
        __syncthreads();   // before next qt re-stages Asq
    }
}

// ---------------- final BN+ReLU into d_out -----------------------------------
__global__ void bn_apply_kernel(float* __restrict__ out)
{
    size_t i = (size_t)blockIdx.x * blockDim.x + threadIdx.x;
    if (i >= (size_t)ROWS * DCH) return;
    int ch = (int)(i & 127);
    out[i] = fmaxf(0.f, fmaf(g_oraw[i], g_scale[3 * 128 + ch], g_shift[3 * 128 + ch]));
}

// =============================================================================
extern "C" void kernel_launch(void* const* d_in, const int* in_sizes, int n_in,
                              void* d_out, int out_size)
{
    (void)in_sizes; (void)n_in; (void)out_size;
    const float* X     = (const float*)d_in[0];
    const float* STE   = (const float*)d_in[1];
    const float* A     = (const float*)d_in[2];
    const float* Wq    = (const float*)d_in[3];
    const float* gq    = (const float*)d_in[5];
    const float* betaq = (const float*)d_in[6];
    const float* Wk    = (const float*)d_in[7];
    const float* gk    = (const float*)d_in[9];
    const float* betak = (const float*)d_in[10];
    const float* Wv    = (const float*)d_in[11];
    const float* gv    = (const float*)d_in[13];
    const float* betav = (const float*)d_in[14];
    const float* Wo    = (const float*)d_in[15];
    const float* go    = (const float*)d_in[17];
    const float* betao = (const float*)d_in[18];
    float* out = (float*)d_out;

    void *pq, *pk, *pv, *pa, *po;
    cudaGetSymbolAddress(&pq, g_qraw);
    cudaGetSymbolAddress(&pk, g_kraw);
    cudaGetSymbolAddress(&pv, g_vraw);
    cudaGetSymbolAddress(&pa, g_aout);
    cudaGetSymbolAddress(&po, g_oraw);

    const int smem_attn = (16 * KT2PAD + 256 * VPPAD + 256 * AQPAD +
                           NNODES * 16) * (int)sizeof(unsigned);   // ~205 KB
    cudaFuncSetAttribute(attn_mma_kernel, cudaFuncAttributeMaxDynamicSharedMemorySize,
                         smem_attn);

    // 1) adjacency -> bitmap
    build_mask_kernel<<<16, 1024>>>(A);

    // 2) q/k/v projections (split-bf16 3-term, ~fp32 accurate, fused BN stats)
    mma_gemm_kernel<256, true><<<dim3(MBLK, 1, 3), 256>>>(
        X, STE, Wq, Wk, Wv, (float*)pq, (float*)pk, (float*)pv, 0);

    // 3) BN finalize for q/k/v
    bn_finalize_kernel<<<3, 512>>>(gq, betaq, gk, betak, gv, betav, 0);

    // 4) dense tensor-core masked attention v4 (paired LDS.64 layouts)
    attn_mma_kernel<<<dim3(NBT, NH), 512, smem_attn>>>();

    // 5) output projection (split-bf16 3-term, fused BN stats)
    mma_gemm_kernel<128, false><<<dim3(MBLK, 1, 1), 256>>>(
        (float*)pa, nullptr, Wo, Wo, Wo, (float*)po, (float*)po, (float*)po, 3);

    // 6) BN finalize for output
    bn_finalize_kernel<<<1, 512>>>(go, betao, go, betao, go, betao, 3);

    // 7) BN + ReLU -> d_out
    bn_apply_kernel<<<(ROWS * DCH + 255) / 256, 256>>>(out);
}

// round 11
// speedup vs baseline: 1.3628x; 1.0772x over previous
#include <cuda_runtime.h>
#include <cuda_bf16.h>
#include <math.h>

// Problem constants
#define ROWS   49152      // B*T*N = 8*12*512
#define DCH    128        // D
#define NNODES 512        // N
#define NBT    96         // B*T
#define NH     4          // heads (d)
#define MBLK   384        // ROWS / 128

// attention smem strides (units: 4B words)
#define KT2PAD 1032       // Ktp row stride: [16][1032], conflict-free LDS.64
#define VPPAD  72         // Vh/Vl row stride: [128][72], conflict-free LDS.64
#define AQPAD  36         // Asq row stride, [256][36]

// GEMM smem pads (bf16-pair words)
#define APAD 20           // A row stride in words (16 used)
#define BPAD 136          // B kpair stride in words

// pre-split W regions (pairword granularity)
#define WOFF_O 49152      // q:0, k:16384, v:32768, o:49152
#define WTOTAL 57344      // 3*16384 + 64*128

// ---------------- scratch (device globals; no cudaMalloc allowed) ----------
__device__ float    g_qraw[ROWS * DCH];
__device__ float    g_kraw[ROWS * DCH];
__device__ float    g_vraw[ROWS * DCH];
__device__ float    g_aout[ROWS * DCH];
__device__ float    g_oraw[ROWS * DCH];
__device__ unsigned g_mask[NNODES * 16];      // A>0 bitmap: row n, 16 words
__device__ unsigned g_WH[WTOTAL], g_WL[WTOTAL]; // pre-split packed bf16 weights
// deterministic BN partials: [z in 0..3][block 0..383][ch 0..127]
__device__ float g_psum[4 * MBLK * DCH];
__device__ float g_psumsq[4 * MBLK * DCH];
__device__ float g_scale[4 * DCH];
__device__ float g_shift[4 * DCH];

// ---------------- helpers ----------------------------------------------------
__device__ __forceinline__ unsigned f2tf32(float f) {
    unsigned r;
    asm("cvt.rna.tf32.f32 %0, %1;" : "=r"(r) : "f"(f));
    return r;
}

__device__ __forceinline__ unsigned bf16x2pk(float hi, float lo) {
    unsigned r;
    asm("cvt.rn.bf16x2.f32 %0, %1, %2;" : "=r"(r) : "f"(hi), "f"(lo));
    return r;   // low 16 bits = bf16(lo), high = bf16(hi)
}

__device__ __forceinline__ float ex2f(float x) {
    float r;
    asm("ex2.approx.f32 %0, %1;" : "=f"(r) : "f"(x));
    return r;
}

// split packed pair (p0 even, p1 odd) into hi/lo packed words
__device__ __forceinline__ void packsplit(float p0, float p1,
                                          unsigned& hi, unsigned& lo) {
    hi = bf16x2pk(p1, p0);
    float f0 = __uint_as_float(hi << 16);
    float f1 = __uint_as_float(hi & 0xffff0000u);
    lo = bf16x2pk(p1 - f1, p0 - f0);
}

__device__ __forceinline__ void mma_tf32(float* c, const unsigned* a, const unsigned* b) {
    asm volatile(
        "mma.sync.aligned.m16n8k8.row.col.f32.tf32.tf32.f32 "
        "{%0,%1,%2,%3}, {%4,%5,%6,%7}, {%8,%9}, {%0,%1,%2,%3};\n"
        : "+f"(c[0]), "+f"(c[1]), "+f"(c[2]), "+f"(c[3])
        : "r"(a[0]), "r"(a[1]), "r"(a[2]), "r"(a[3]), "r"(b[0]), "r"(b[1]));
}

__device__ __forceinline__ void mma_bf16(float* c, const unsigned* a, const unsigned* b) {
    asm volatile(
        "mma.sync.aligned.m16n8k16.row.col.f32.bf16.bf16.f32 "
        "{%0,%1,%2,%3}, {%4,%5,%6,%7}, {%8,%9}, {%0,%1,%2,%3};\n"
        : "+f"(c[0]), "+f"(c[1]), "+f"(c[2]), "+f"(c[3])
        : "r"(a[0]), "r"(a[1]), "r"(a[2]), "r"(a[3]), "r"(b[0]), "r"(b[1]));
}

__device__ __forceinline__ void split_bf16(float v, unsigned short& h, unsigned short& l) {
    __nv_bfloat16 hb = __float2bfloat16_rn(v);
    float hf = __bfloat162float(hb);
    __nv_bfloat16 lb = __float2bfloat16_rn(v - hf);
    h = *(unsigned short*)&hb;
    l = *(unsigned short*)&lb;
}

__device__ __forceinline__ unsigned pack2(unsigned short lo, unsigned short hi) {
    return (unsigned)lo | ((unsigned)hi << 16);   // low 16 = even-k element
}

// ---------------- adjacency bitmap (warp per row, ballot) --------------------
__global__ void build_mask_kernel(const float* __restrict__ A)
{
    int row  = (blockIdx.x * blockDim.x + threadIdx.x) >> 5;
    int lane = threadIdx.x & 31;
    if (row >= NNODES) return;
    for (int w = 0; w < 16; w++) {
        float a = A[row * NNODES + w * 32 + lane];
        unsigned bal = __ballot_sync(0xffffffffu, a > 0.f);
        if (lane == 0) g_mask[row * 16 + w] = bal;
    }
}

// ---------------- pre-split weights into packed bf16 hi/lo pairwords --------
__global__ void presplit_w_kernel(const float* __restrict__ Wq,
                                  const float* __restrict__ Wk,
                                  const float* __restrict__ Wv,
                                  const float* __restrict__ Wo)
{
    int idx = blockIdx.x * blockDim.x + threadIdx.x;
    if (idx >= WTOTAL) return;
    const float* W;
    int off;
    if (idx < 16384)      { W = Wq; off = 0; }
    else if (idx < 32768) { W = Wk; off = 16384; }
    else if (idx < 49152) { W = Wv; off = 32768; }
    else                  { W = Wo; off = WOFF_O; }
    int local = idx - off;
    int kp = local >> 7, n = local & 127;
    float v0 = W[(size_t)(2 * kp) * 128 + n];
    float v1 = W[(size_t)(2 * kp + 1) * 128 + n];
    unsigned short h0, l0, h1, l1;
    split_bf16(v0, h0, l0);
    split_bf16(v1, h1, l1);
    g_WH[idx] = pack2(h0, h1);
    g_WL[idx] = pack2(l0, l1);
}

// ---------------- split-bf16 tensor GEMM, 128x128 tile, BK=32 ---------------
// Y = A @ W via AhBh + AlBh + AhBl (~fp32 accuracy). Weights pre-split in
// g_WH/g_WL (wbase + z*wstep selects the matrix) -> B staging is a pure copy.
// Bias dropped (cancels in BN). CAT: A=[X|STE], KDIM=256. Fused BN partials.
template <int KDIM, bool CAT>
__global__ __launch_bounds__(256)
void mma_gemm_kernel(const float* __restrict__ A0, const float* __restrict__ A1,
                     int wbase, int wstep,
                     float* __restrict__ Y0, float* __restrict__ Y1,
                     float* __restrict__ Y2, int zbase)
{
    __shared__ unsigned AsH[128 * APAD], AsL[128 * APAD];   // [row][kpair]
    __shared__ unsigned BsH[16 * BPAD],  BsL[16 * BPAD];    // [kpair][n]
    __shared__ float ssum[2][128], ssq[2][128];

    const int z = blockIdx.z;
    float* Y = (z == 0) ? Y0 : (z == 1) ? Y1 : Y2;
    const unsigned* WH = g_WH + wbase + z * wstep;
    const unsigned* WL = g_WL + wbase + z * wstep;

    const int tid  = threadIdx.x;
    const int lane = tid & 31;
    const int wid  = tid >> 5;
    const int wm   = wid >> 2;
    const int wn   = wid & 3;
    const int row0 = blockIdx.x * 128;
    const int g    = lane >> 2;
    const int tg   = lane & 3;

    float acc[4][4][4];
#pragma unroll
    for (int mt = 0; mt < 4; mt++)
#pragma unroll
        for (int nt = 0; nt < 4; nt++)
#pragma unroll
            for (int q = 0; q < 4; q++) acc[mt][nt][q] = 0.f;

    for (int k0 = 0; k0 < KDIM; k0 += 32) {
        const float* Abase;
        int kofs;
        if (CAT) {
            if (k0 < 128) { Abase = A0; kofs = k0; }
            else          { Abase = A1; kofs = k0 - 128; }
        } else { Abase = A0; kofs = k0; }

        // A tile: split in-kernel (rows unique per CTA)
#pragma unroll
        for (int t = 0; t < 4; t++) {
            int i  = tid + 256 * t;
            int r  = i >> 3;
            int kq = (i & 7) << 2;
            float4 v = *(const float4*)(Abase + (size_t)(row0 + r) * 128 + kofs + kq);
            unsigned short hx, lx, hy, ly, hz, lz, hw, lw;
            split_bf16(v.x, hx, lx); split_bf16(v.y, hy, ly);
            split_bf16(v.z, hz, lz); split_bf16(v.w, hw, lw);
            int o = r * APAD + (kq >> 1);
            AsH[o + 0] = pack2(hx, hy);  AsH[o + 1] = pack2(hz, hw);
            AsL[o + 0] = pack2(lx, ly);  AsL[o + 1] = pack2(lz, lw);
        }
        // B tile: direct copy of pre-split pairwords
        {
            const int kp0 = k0 >> 1;
#pragma unroll
            for (int t = 0; t < 2; t++) {
                int i  = tid + 256 * t;
                int kp = i >> 5;
                int n4 = (i & 31) << 2;
                uint4 hv = *(const uint4*)&WH[(size_t)(kp0 + kp) * 128 + n4];
                uint4 lv = *(const uint4*)&WL[(size_t)(kp0 + kp) * 128 + n4];
                *(uint4*)&BsH[kp * BPAD + n4] = hv;
                *(uint4*)&BsL[kp * BPAD + n4] = lv;
            }
        }
        __syncthreads();

#pragma unroll
        for (int s = 0; s < 2; s++) {
            const int kb = s * 8;
            unsigned afH[4][4], afL[4][4];
#pragma unroll
            for (int mt = 0; mt < 4; mt++) {
                int rB = wm * 64 + mt * 16;
                afH[mt][0] = AsH[(rB + g) * APAD + kb + tg];
                afH[mt][1] = AsH[(rB + 8 + g) * APAD + kb + tg];
                afH[mt][2] = AsH[(rB + g) * APAD + kb + 4 + tg];
                afH[mt][3] = AsH[(rB + 8 + g) * APAD + kb + 4 + tg];
                afL[mt][0] = AsL[(rB + g) * APAD + kb + tg];
                afL[mt][1] = AsL[(rB + 8 + g) * APAD + kb + tg];
                afL[mt][2] = AsL[(rB + g) * APAD + kb + 4 + tg];
                afL[mt][3] = AsL[(rB + 8 + g) * APAD + kb + 4 + tg];
            }
#pragma unroll
            for (int nt = 0; nt < 4; nt++) {
                int cc = wn * 32 + nt * 8 + g;
                unsigned bfH[2], bfL[2];
                bfH[0] = BsH[(kb + tg) * BPAD + cc];
                bfH[1] = BsH[(kb + 4 + tg) * BPAD + cc];
                bfL[0] = BsL[(kb + tg) * BPAD + cc];
                bfL[1] = BsL[(kb + 4 + tg) * BPAD + cc];
#pragma unroll
                for (int mt = 0; mt < 4; mt++) {
                    mma_bf16(acc[mt][nt], afH[mt], bfH);
                    mma_bf16(acc[mt][nt], afL[mt], bfH);
                    mma_bf16(acc[mt][nt], afH[mt], bfL);
                }
            }
        }
        __syncthreads();
    }

#pragma unroll
    for (int nt = 0; nt < 4; nt++) {
        float se = 0.f, so = 0.f, qe = 0.f, qo = 0.f;
#pragma unroll
        for (int mt = 0; mt < 4; mt++) {
            float c0 = acc[mt][nt][0], c1 = acc[mt][nt][1];
            float c2 = acc[mt][nt][2], c3 = acc[mt][nt][3];
            int r   = row0 + wm * 64 + mt * 16 + g;
            int col = wn * 32 + nt * 8 + tg * 2;
            *(float2*)(Y + (size_t)r * 128 + col)       = make_float2(c0, c1);
            *(float2*)(Y + (size_t)(r + 8) * 128 + col) = make_float2(c2, c3);
            se += c0 + c2;  so += c1 + c3;
            qe += c0 * c0 + c2 * c2;  qo += c1 * c1 + c3 * c3;
        }
#pragma unroll
        for (int o = 4; o < 32; o <<= 1) {
            se += __shfl_xor_sync(0xffffffffu, se, o);
            so += __shfl_xor_sync(0xffffffffu, so, o);
            qe += __shfl_xor_sync(0xffffffffu, qe, o);
            qo += __shfl_xor_sync(0xffffffffu, qo, o);
        }
        if (lane < 4) {
            int col = wn * 32 + nt * 8 + lane * 2;
            ssum[wm][col]     = se;  ssum[wm][col + 1] = so;
            ssq[wm][col]      = qe;  ssq[wm][col + 1]  = qo;
        }
    }
    __syncthreads();
    if (tid < 128) {
        int slot = ((zbase + z) * MBLK + blockIdx.x) * DCH + tid;
        g_psum[slot]   = ssum[0][tid] + ssum[1][tid];
        g_psumsq[slot] = ssq[0][tid] + ssq[1][tid];
    }
}

// ---------------- BN finalize: reduce 384 partials (parallel) ---------------
__global__ void bn_finalize_kernel(const float* __restrict__ g0, const float* __restrict__ be0,
                                   const float* __restrict__ g1, const float* __restrict__ be1,
                                   const float* __restrict__ g2, const float* __restrict__ be2,
                                   int zbase)
{
    __shared__ float ss[512], sq[512];
    int z = blockIdx.x;
    const float* g  = (z == 0) ? g0 : (z == 1) ? g1 : g2;
    const float* be = (z == 0) ? be0 : (z == 1) ? be1 : be2;
    int ch = threadIdx.x & 127, part = threadIdx.x >> 7;
    float s = 0.f, s2 = 0.f;
    for (int b = part; b < MBLK; b += 4) {
        int slot = ((zbase + z) * MBLK + b) * DCH + ch;
        s  += g_psum[slot];
        s2 += g_psumsq[slot];
    }
    ss[threadIdx.x] = s;  sq[threadIdx.x] = s2;
    __syncthreads();
    if (threadIdx.x < 128) {
        s  = ss[ch] + ss[ch + 128] + ss[ch + 256] + ss[ch + 384];
        s2 = sq[ch] + sq[ch + 128] + sq[ch + 256] + sq[ch + 384];
        const float inv_cnt = 1.f / (float)ROWS;
        float mu  = s * inv_cnt;
        float var = s2 * inv_cnt - mu * mu;
        float sc  = g[ch] * rsqrtf(var + 1e-5f);
        g_scale[(zbase + z) * 128 + ch] = sc;
        g_shift[(zbase + z) * 128 + ch] = be[ch] - mu * sc;
    }
}

// ---------------- dense tensor-core masked flash-attention v6 ---------------
// 512 threads, 16 warps, warp owns 16 q rows of a 256-row super-tile.
// QK: tf32 m16n8k8 (score precision). PV: SPLIT-bf16 m16n8k16, 3 terms
// (Phi*Vh + Plo*Vh + Phi*Vl, residual ~2^-16) — accumulator layout matches
// the bf16 A-operand layout, so no transpose. Softmax denominator computed
// via an extra ones-column mma (every lane ends up holding its row's l).
// No-max softmax: p = 2^(log2e/2 * s - 30*log2e); masked -> exact 0.
__global__ __launch_bounds__(512)
void attn_mma_kernel()
{
    extern __shared__ unsigned smu[];
    unsigned* Ktp = smu;                          // [16][KT2PAD]  K^T tf32 paired
    unsigned* Vh  = Ktp + 16 * KT2PAD;            // [128][VPPAD]  V hi bf16 paired
    unsigned* Vl  = Vh  + 128 * VPPAD;            // [128][VPPAD]  V lo bf16 paired
    unsigned* Asq = Vl  + 128 * VPPAD;            // [256][AQPAD]  Q tile tf32
    unsigned* smk = Asq + 256 * AQPAD;            // [512][16]     mask bitmap

    const int bt   = blockIdx.x;
    const int h    = blockIdx.y;
    const int tid  = threadIdx.x;
    const int lane = tid & 31;
    const int wid  = tid >> 5;                    // 0..15
    const int g    = lane >> 2;
    const int tg   = lane & 3;
    const size_t rowbase = (size_t)bt * NNODES;
    const int cb = h * 32;

    const float scq = g_scale[0 * 128 + cb + lane], shq = g_shift[0 * 128 + cb + lane];
    const float sck = g_scale[1 * 128 + cb + lane], shk = g_shift[1 * 128 + cb + lane];
    const float scv = g_scale[2 * 128 + cb + lane], shv = g_shift[2 * 128 + cb + lane];

    // stage K -> Ktp (tf32, channel-paired) and V -> Vh/Vl (bf16 split, paired)
    {
        const int c     = lane;
        const int krow  = (c >> 3) * 4 + (c & 3);
        const int khalf = (c & 7) >> 2;
        for (int idx = tid; idx < NNODES * 32; idx += 512) {
            int n = idx >> 5;                     // (idx & 31) == lane
            float kv = g_kraw[(rowbase + n) * 128 + cb + c];
            Ktp[krow * KT2PAD + 2 * n + khalf] =
                f2tf32(fmaxf(0.f, fmaf(kv, sck, shk)));
            float vv = g_vraw[(rowbase + n) * 128 + cb + c];
            float vfull = fmaxf(0.f, fmaf(vv, scv, shv));
            __nv_bfloat16 vhb = __float2bfloat16_rn(vfull);
            float vhf = __bfloat162float(vhb);
            __nv_bfloat16 vlb = __float2bfloat16_rn(vfull - vhf);
            int p = n >> 1, q = p & 7;
            int vofs = ((p >> 3) * 4 + (q & 3)) * VPPAD + 2 * c + (q >> 2);
            ((unsigned short*)&Vh[vofs])[n & 1] = *(unsigned short*)&vhb;
            ((unsigned short*)&Vl[vofs])[n & 1] = *(unsigned short*)&vlb;
        }
    }
    for (int idx = tid; idx < NNODES * 16; idx += 512) smk[idx] = g_mask[idx];
    __syncthreads();

    const int q0 = wid * 16;
    const float K1 = 0.72134752044f;   // log2(e)/2
    const float K0 = -43.2808512267f;  // -30*log2(e)
    const unsigned BONES0 = 0x3F803F80u;   // bf16 1.0 pair
    unsigned bones[2] = {BONES0, BONES0};

    for (int qt = 0; qt < 2; qt++) {
        for (int idx = tid; idx < 256 * 32; idx += 512) {
            int r = idx >> 5;
            float qv = g_qraw[(rowbase + qt * 256 + r) * 128 + cb + lane];
            Asq[r * AQPAD + lane] = f2tf32(fmaxf(0.f, fmaf(qv, scq, shq)));
        }
        __syncthreads();

        const int r0 = qt * 256 + q0 + g;
        const int r1 = r0 + 8;

        // hoist Q fragments (invariant across kv strips)
        unsigned aq[4][4];
#pragma unroll
        for (int ks = 0; ks < 4; ks++) {
            const int kb = ks * 8;
            aq[ks][0] = Asq[(q0 + g) * AQPAD + kb + tg];
            aq[ks][1] = Asq[(q0 + g + 8) * AQPAD + kb + tg];
            aq[ks][2] = Asq[(q0 + g) * AQPAD + kb + tg + 4];
            aq[ks][3] = Asq[(q0 + g + 8) * AQPAD + kb + tg + 4];
        }

        float o[4][4], o5[4];
#pragma unroll
        for (int nt = 0; nt < 4; nt++)
#pragma unroll
            for (int q = 0; q < 4; q++) o[nt][q] = 0.f;
        o5[0] = 0.f; o5[1] = 0.f; o5[2] = 0.f; o5[3] = 0.f;

        for (int kv = 0; kv < 16; kv++) {
            const int n0 = kv * 32;

            // ---- S = Q K^T (16x32 strip), paired LDS.64 B-frags ----
            float c[4][4];
#pragma unroll
            for (int nt = 0; nt < 4; nt++) {
                c[nt][0] = 0.f; c[nt][1] = 0.f; c[nt][2] = 0.f; c[nt][3] = 0.f;
            }
#pragma unroll
            for (int ks = 0; ks < 4; ks++) {
#pragma unroll
                for (int nt = 0; nt < 4; nt++) {
                    int cc = n0 + nt * 8 + g;
                    uint2 b2 = *(const uint2*)&Ktp[(ks * 4 + tg) * KT2PAD + 2 * cc];
                    unsigned b[2] = {b2.x, b2.y};
                    mma_tf32(c[nt], aq[ks], b);
                }
            }

            // ---- masked exp (no max tracking) ----
            unsigned w0 = smk[r0 * 16 + kv];
            unsigned w1 = smk[r1 * 16 + kv];
#pragma unroll
            for (int nt = 0; nt < 4; nt++) {
                int sh = nt * 8 + 2 * tg;
                c[nt][0] = ((w0 >> sh) & 1u)       ? ex2f(fmaf(c[nt][0], K1, K0)) : 0.f;
                c[nt][1] = ((w0 >> (sh + 1)) & 1u) ? ex2f(fmaf(c[nt][1], K1, K0)) : 0.f;
                c[nt][2] = ((w1 >> sh) & 1u)       ? ex2f(fmaf(c[nt][2], K1, K0)) : 0.f;
                c[nt][3] = ((w1 >> (sh + 1)) & 1u) ? ex2f(fmaf(c[nt][3], K1, K0)) : 0.f;
            }

            // ---- O += P V (split-bf16, no transpose); l via ones-mma ----
#pragma unroll
            for (int kt = 0; kt < 2; kt++) {
                unsigned ahi[4], alo[4];
                packsplit(c[2 * kt][0],     c[2 * kt][1],     ahi[0], alo[0]);
                packsplit(c[2 * kt][2],     c[2 * kt][3],     ahi[1], alo[1]);
                packsplit(c[2 * kt + 1][0], c[2 * kt + 1][1], ahi[2], alo[2]);
                packsplit(c[2 * kt + 1][2], c[2 * kt + 1][3], ahi[3], alo[3]);
                const int pblk = kv * 2 + kt;
#pragma unroll
                for (int nt = 0; nt < 4; nt++) {
                    int bofs = (pblk * 4 + tg) * VPPAD + 2 * (nt * 8 + g);
                    uint2 bh2 = *(const uint2*)&Vh[bofs];
                    uint2 bl2 = *(const uint2*)&Vl[bofs];
                    unsigned bh[2] = {bh2.x, bh2.y};
                    unsigned bl[2] = {bl2.x, bl2.y};
                    mma_bf16(o[nt], ahi, bh);
                    mma_bf16(o[nt], alo, bh);
                    mma_bf16(o[nt], ahi, bl);
                }
                mma_bf16(o5, ahi, bones);
                mma_bf16(o5, alo, bones);
            }
        }

        // ---- epilogue: normalize, write (o5[0]=l(row g), o5[2]=l(row g+8)) ----
        float il0 = 1.f / o5[0], il1 = 1.f / o5[2];
#pragma unroll
        for (int nt = 0; nt < 4; nt++) {
            int col = cb + nt * 8 + 2 * tg;
            *(float2*)&g_aout[(rowbase + r0) * 128 + col] =
                make_float2(o[nt][0] * il0, o[nt][1] * il0);
            *(float2*)&g_aout[(rowbase + r1) * 128 + col] =
                make_float2(o[nt][2] * il1, o[nt][3] * il1);
        }
        __syncthreads();   // before next qt re-stages Asq
    }
}

// ---------------- final BN+ReLU into d_out (float4) --------------------------
__global__ void bn_apply_kernel(float* __restrict__ out)
{
    size_t i4 = (size_t)blockIdx.x * blockDim.x + threadIdx.x;
    if (i4 >= (size_t)ROWS * DCH / 4) return;
    int c0 = (int)((i4 * 4) & 127);
    float4 v = *(const float4*)&g_oraw[i4 * 4];
    float4 sc = *(const float4*)&g_scale[3 * 128 + c0];
    float4 sh = *(const float4*)&g_shift[3 * 128 + c0];
    float4 r;
    r.x = fmaxf(0.f, fmaf(v.x, sc.x, sh.x));
    r.y = fmaxf(0.f, fmaf(v.y, sc.y, sh.y));
    r.z = fmaxf(0.f, fmaf(v.z, sc.z, sh.z));
    r.w = fmaxf(0.f, fmaf(v.w, sc.w, sh.w));
    *(float4*)&out[i4 * 4] = r;
}

// =============================================================================
extern "C" void kernel_launch(void* const* d_in, const int* in_sizes, int n_in,
                              void* d_out, int out_size)
{
    (void)in_sizes; (void)n_in; (void)out_size;
    const float* X     = (const float*)d_in[0];
    const float* STE   = (const float*)d_in[1];
    const float* A     = (const float*)d_in[2];
    const float* Wq    = (const float*)d_in[3];
    const float* gq    = (const float*)d_in[5];
    const float* betaq = (const float*)d_in[6];
    const float* Wk    = (const float*)d_in[7];
    const float* gk    = (const float*)d_in[9];
    const float* betak = (const float*)d_in[10];
    const float* Wv    = (const float*)d_in[11];
    const float* gv    = (const float*)d_in[13];
    const float* betav = (const float*)d_in[14];
    const float* Wo    = (const float*)d_in[15];
    const float* go    = (const float*)d_in[17];
    const float* betao = (const float*)d_in[18];
    float* out = (float*)d_out;

    void *pq, *pk, *pv, *pa, *po;
    cudaGetSymbolAddress(&pq, g_qraw);
    cudaGetSymbolAddress(&pk, g_kraw);
    cudaGetSymbolAddress(&pv, g_vraw);
    cudaGetSymbolAddress(&pa, g_aout);
    cudaGetSymbolAddress(&po, g_oraw);

    const int smem_attn = (16 * KT2PAD + 2 * 128 * VPPAD + 256 * AQPAD +
                           NNODES * 16) * (int)sizeof(unsigned);   // ~204.5 KB
    cudaFuncSetAttribute(attn_mma_kernel, cudaFuncAttributeMaxDynamicSharedMemorySize,
                         smem_attn);

    // 1) adjacency -> bitmap; pre-split weights
    build_mask_kernel<<<16, 1024>>>(A);
    presplit_w_kernel<<<(WTOTAL + 255) / 256, 256>>>(Wq, Wk, Wv, Wo);

    // 2) q/k/v projections (split-bf16 3-term, pre-split W, fused BN stats)
    mma_gemm_kernel<256, true><<<dim3(MBLK, 1, 3), 256>>>(
        X, STE, 0, 16384, (float*)pq, (float*)pk, (float*)pv, 0);

    // 3) BN finalize for q/k/v
    bn_finalize_kernel<<<3, 512>>>(gq, betaq, gk, betak, gv, betav, 0);

    // 4) dense tensor-core masked attention v6 (split-bf16 PV, ones-mma l)
    attn_mma_kernel<<<dim3(NBT, NH), 512, smem_attn>>>();

    // 5) output projection (split-bf16 3-term, pre-split W, fused BN stats)
    mma_gemm_kernel<128, false><<<dim3(MBLK, 1, 1), 256>>>(
        (float*)pa, nullptr, WOFF_O, 0, (float*)po, (float*)po, (float*)po, 3);

    // 6) BN finalize for output
    bn_finalize_kernel<<<1, 512>>>(go, betao, go, betao, go, betao, 3);

    // 7) BN + ReLU -> d_out
    bn_apply_kernel<<<(ROWS * DCH / 4 + 255) / 256, 256>>>(out);
}

// round 12
// speedup vs baseline: 1.4611x; 1.0722x over previous
#include <cuda_runtime.h>
#include <cuda_bf16.h>
#include <math.h>

// Problem constants
#define ROWS   49152      // B*T*N = 8*12*512
#define DCH    128        // D
#define NNODES 512        // N
#define NBT    96         // B*T
#define NH     4          // heads (d)
#define MBLK   384        // ROWS / 128

// attention smem strides (units: 4B words)
#define KT2PAD 1032       // Ktp row stride: [16][1032], conflict-free LDS.64
#define VPPAD  72         // Vh/Vl row stride: [128][72], conflict-free LDS.64
#define AQPAD  36         // Asq row stride, [256][36]

// GEMM smem pads (bf16-pair words)
#define APAD 20           // A row stride in words (16 used)
#define BPAD 136          // B kpair stride in words

// pre-split W regions (pairword granularity)
#define WOFF_O 49152      // q:0, k:16384, v:32768, o:49152
#define WTOTAL 57344      // 3*16384 + 64*128

// ---------------- scratch (device globals; no cudaMalloc allowed) ----------
__device__ float    g_qraw[ROWS * DCH];
__device__ float    g_kraw[ROWS * DCH];
__device__ float    g_vraw[ROWS * DCH];
__device__ float    g_aout[ROWS * DCH];
__device__ float    g_oraw[ROWS * DCH];
__device__ unsigned g_mask[NNODES * 16];      // A>0 bitmap: row n, 16 words
__device__ unsigned g_WH[WTOTAL], g_WL[WTOTAL]; // pre-split packed bf16 weights
// deterministic BN partials, layout [z][ch][block]: slot=(z*128+ch)*384+b
__device__ float g_psum[4 * DCH * MBLK];
__device__ float g_psumsq[4 * DCH * MBLK];
__device__ float g_scale[4 * DCH];
__device__ float g_shift[4 * DCH];

// ---------------- helpers ----------------------------------------------------
__device__ __forceinline__ unsigned f2tf32(float f) {
    unsigned r;
    asm("cvt.rna.tf32.f32 %0, %1;" : "=r"(r) : "f"(f));
    return r;
}

__device__ __forceinline__ unsigned bf16x2pk(float hi, float lo) {
    unsigned r;
    asm("cvt.rn.bf16x2.f32 %0, %1, %2;" : "=r"(r) : "f"(hi), "f"(lo));
    return r;   // low 16 bits = bf16(lo), high = bf16(hi)
}

__device__ __forceinline__ float ex2f(float x) {
    float r;
    asm("ex2.approx.f32 %0, %1;" : "=f"(r) : "f"(x));
    return r;
}

// split packed pair (p0 even, p1 odd) into hi/lo packed words
__device__ __forceinline__ void packsplit(float p0, float p1,
                                          unsigned& hi, unsigned& lo) {
    hi = bf16x2pk(p1, p0);
    float f0 = __uint_as_float(hi << 16);
    float f1 = __uint_as_float(hi & 0xffff0000u);
    lo = bf16x2pk(p1 - f1, p0 - f0);
}

__device__ __forceinline__ void mma_tf32(float* c, const unsigned* a, const unsigned* b) {
    asm volatile(
        "mma.sync.aligned.m16n8k8.row.col.f32.tf32.tf32.f32 "
        "{%0,%1,%2,%3}, {%4,%5,%6,%7}, {%8,%9}, {%0,%1,%2,%3};\n"
        : "+f"(c[0]), "+f"(c[1]), "+f"(c[2]), "+f"(c[3])
        : "r"(a[0]), "r"(a[1]), "r"(a[2]), "r"(a[3]), "r"(b[0]), "r"(b[1]));
}

__device__ __forceinline__ void mma_bf16(float* c, const unsigned* a, const unsigned* b) {
    asm volatile(
        "mma.sync.aligned.m16n8k16.row.col.f32.bf16.bf16.f32 "
        "{%0,%1,%2,%3}, {%4,%5,%6,%7}, {%8,%9}, {%0,%1,%2,%3};\n"
        : "+f"(c[0]), "+f"(c[1]), "+f"(c[2]), "+f"(c[3])
        : "r"(a[0]), "r"(a[1]), "r"(a[2]), "r"(a[3]), "r"(b[0]), "r"(b[1]));
}

__device__ __forceinline__ void split_bf16(float v, unsigned short& h, unsigned short& l) {
    __nv_bfloat16 hb = __float2bfloat16_rn(v);
    float hf = __bfloat162float(hb);
    __nv_bfloat16 lb = __float2bfloat16_rn(v - hf);
    h = *(unsigned short*)&hb;
    l = *(unsigned short*)&lb;
}

__device__ __forceinline__ unsigned pack2(unsigned short lo, unsigned short hi) {
    return (unsigned)lo | ((unsigned)hi << 16);   // low 16 = even-k element
}

// ---------------- setup: adjacency bitmap + weight pre-split (merged) -------
// blocks [0,16): mask rows (warp per row). blocks [16,72): W pre-split.
__global__ void setup_kernel(const float* __restrict__ A,
                             const float* __restrict__ Wq,
                             const float* __restrict__ Wk,
                             const float* __restrict__ Wv,
                             const float* __restrict__ Wo)
{
    if (blockIdx.x < 16) {
        int row  = (blockIdx.x * 1024 + threadIdx.x) >> 5;
        int lane = threadIdx.x & 31;
        for (int w = 0; w < 16; w++) {
            float a = A[row * NNODES + w * 32 + lane];
            unsigned bal = __ballot_sync(0xffffffffu, a > 0.f);
            if (lane == 0) g_mask[row * 16 + w] = bal;
        }
    } else {
        int idx = (blockIdx.x - 16) * 1024 + threadIdx.x;
        if (idx >= WTOTAL) return;
        const float* W;
        int off;
        if (idx < 16384)      { W = Wq; off = 0; }
        else if (idx < 32768) { W = Wk; off = 16384; }
        else if (idx < 49152) { W = Wv; off = 32768; }
        else                  { W = Wo; off = WOFF_O; }
        int local = idx - off;
        int kp = local >> 7, n = local & 127;
        float v0 = W[(size_t)(2 * kp) * 128 + n];
        float v1 = W[(size_t)(2 * kp + 1) * 128 + n];
        unsigned short h0, l0, h1, l1;
        split_bf16(v0, h0, l0);
        split_bf16(v1, h1, l1);
        g_WH[idx] = pack2(h0, h1);
        g_WL[idx] = pack2(l0, l1);
    }
}

// ---------------- split-bf16 tensor GEMM, 128x128 tile, BK=32 ---------------
// Y = A @ W via AhBh + AlBh + AhBl (~fp32 accuracy). Weights pre-split in
// g_WH/g_WL (wbase + z*wstep selects the matrix) -> B staging is a pure copy.
// Bias dropped (cancels in BN). CAT: A=[X|STE], KDIM=256. Fused BN partials
// written in [z][ch][block] layout for the fast finalize.
template <int KDIM, bool CAT>
__global__ __launch_bounds__(256)
void mma_gemm_kernel(const float* __restrict__ A0, const float* __restrict__ A1,
                     int wbase, int wstep,
                     float* __restrict__ Y0, float* __restrict__ Y1,
                     float* __restrict__ Y2, int zbase)
{
    __shared__ unsigned AsH[128 * APAD], AsL[128 * APAD];   // [row][kpair]
    __shared__ unsigned BsH[16 * BPAD],  BsL[16 * BPAD];    // [kpair][n]
    __shared__ float ssum[2][128], ssq[2][128];

    const int z = blockIdx.z;
    float* Y = (z == 0) ? Y0 : (z == 1) ? Y1 : Y2;
    const unsigned* WH = g_WH + wbase + z * wstep;
    const unsigned* WL = g_WL + wbase + z * wstep;

    const int tid  = threadIdx.x;
    const int lane = tid & 31;
    const int wid  = tid >> 5;
    const int wm   = wid >> 2;
    const int wn   = wid & 3;
    const int row0 = blockIdx.x * 128;
    const int g    = lane >> 2;
    const int tg   = lane & 3;

    float acc[4][4][4];
#pragma unroll
    for (int mt = 0; mt < 4; mt++)
#pragma unroll
        for (int nt = 0; nt < 4; nt++)
#pragma unroll
            for (int q = 0; q < 4; q++) acc[mt][nt][q] = 0.f;

    for (int k0 = 0; k0 < KDIM; k0 += 32) {
        const float* Abase;
        int kofs;
        if (CAT) {
            if (k0 < 128) { Abase = A0; kofs = k0; }
            else          { Abase = A1; kofs = k0 - 128; }
        } else { Abase = A0; kofs = k0; }

        // A tile: split in-kernel (rows unique per CTA)
#pragma unroll
        for (int t = 0; t < 4; t++) {
            int i  = tid + 256 * t;
            int r  = i >> 3;
            int kq = (i & 7) << 2;
            float4 v = *(const float4*)(Abase + (size_t)(row0 + r) * 128 + kofs + kq);
            unsigned short hx, lx, hy, ly, hz, lz, hw, lw;
            split_bf16(v.x, hx, lx); split_bf16(v.y, hy, ly);
            split_bf16(v.z, hz, lz); split_bf16(v.w, hw, lw);
            int o = r * APAD + (kq >> 1);
            AsH[o + 0] = pack2(hx, hy);  AsH[o + 1] = pack2(hz, hw);
            AsL[o + 0] = pack2(lx, ly);  AsL[o + 1] = pack2(lz, lw);
        }
        // B tile: direct copy of pre-split pairwords
        {
            const int kp0 = k0 >> 1;
#pragma unroll
            for (int t = 0; t < 2; t++) {
                int i  = tid + 256 * t;
                int kp = i >> 5;
                int n4 = (i & 31) << 2;
                uint4 hv = *(const uint4*)&WH[(size_t)(kp0 + kp) * 128 + n4];
                uint4 lv = *(const uint4*)&WL[(size_t)(kp0 + kp) * 128 + n4];
                *(uint4*)&BsH[kp * BPAD + n4] = hv;
                *(uint4*)&BsL[kp * BPAD + n4] = lv;
            }
        }
        __syncthreads();

#pragma unroll
        for (int s = 0; s < 2; s++) {
            const int kb = s * 8;
            unsigned afH[4][4], afL[4][4];
#pragma unroll
            for (int mt = 0; mt < 4; mt++) {
                int rB = wm * 64 + mt * 16;
                afH[mt][0] = AsH[(rB + g) * APAD + kb + tg];
                afH[mt][1] = AsH[(rB + 8 + g) * APAD + kb + tg];
                afH[mt][2] = AsH[(rB + g) * APAD + kb + 4 + tg];
                afH[mt][3] = AsH[(rB + 8 + g) * APAD + kb + 4 + tg];
                afL[mt][0] = AsL[(rB + g) * APAD + kb + tg];
                afL[mt][1] = AsL[(rB + 8 + g) * APAD + kb + tg];
                afL[mt][2] = AsL[(rB + g) * APAD + kb + 4 + tg];
                afL[mt][3] = AsL[(rB + 8 + g) * APAD + kb + 4 + tg];
            }
#pragma unroll
            for (int nt = 0; nt < 4; nt++) {
                int cc = wn * 32 + nt * 8 + g;
                unsigned bfH[2], bfL[2];
                bfH[0] = BsH[(kb + tg) * BPAD + cc];
                bfH[1] = BsH[(kb + 4 + tg) * BPAD + cc];
                bfL[0] = BsL[(kb + tg) * BPAD + cc];
                bfL[1] = BsL[(kb + 4 + tg) * BPAD + cc];
#pragma unroll
                for (int mt = 0; mt < 4; mt++) {
                    mma_bf16(acc[mt][nt], afH[mt], bfH);
                    mma_bf16(acc[mt][nt], afL[mt], bfH);
                    mma_bf16(acc[mt][nt], afH[mt], bfL);
                }
            }
        }
        __syncthreads();
    }

#pragma unroll
    for (int nt = 0; nt < 4; nt++) {
        float se = 0.f, so = 0.f, qe = 0.f, qo = 0.f;
#pragma unroll
        for (int mt = 0; mt < 4; mt++) {
            float c0 = acc[mt][nt][0], c1 = acc[mt][nt][1];
            float c2 = acc[mt][nt][2], c3 = acc[mt][nt][3];
            int r   = row0 + wm * 64 + mt * 16 + g;
            int col = wn * 32 + nt * 8 + tg * 2;
            *(float2*)(Y + (size_t)r * 128 + col)       = make_float2(c0, c1);
            *(float2*)(Y + (size_t)(r + 8) * 128 + col) = make_float2(c2, c3);
            se += c0 + c2;  so += c1 + c3;
            qe += c0 * c0 + c2 * c2;  qo += c1 * c1 + c3 * c3;
        }
#pragma unroll
        for (int o = 4; o < 32; o <<= 1) {
            se += __shfl_xor_sync(0xffffffffu, se, o);
            so += __shfl_xor_sync(0xffffffffu, so, o);
            qe += __shfl_xor_sync(0xffffffffu, qe, o);
            qo += __shfl_xor_sync(0xffffffffu, qo, o);
        }
        if (lane < 4) {
            int col = wn * 32 + nt * 8 + lane * 2;
            ssum[wm][col]     = se;  ssum[wm][col + 1] = so;
            ssq[wm][col]      = qe;  ssq[wm][col + 1]  = qo;
        }
    }
    __syncthreads();
    if (tid < 128) {
        // [z][ch][block] layout
        int slot = ((zbase + z) * DCH + tid) * MBLK + blockIdx.x;
        g_psum[slot]   = ssum[0][tid] + ssum[1][tid];
        g_psumsq[slot] = ssq[0][tid] + ssq[1][tid];
    }
}

// ---------------- BN finalize v2: warp-per-channel, contiguous loads --------
// grid.x = nz; block = 512 (16 warps). Warp w handles channels w*8..w*8+7;
// per channel each lane sums 12 contiguous floats (3x LDG.128), 5-level shfl.
__global__ void bn_finalize_kernel(const float* __restrict__ g0, const float* __restrict__ be0,
                                   const float* __restrict__ g1, const float* __restrict__ be1,
                                   const float* __restrict__ g2, const float* __restrict__ be2,
                                   int zbase)
{
    int z = blockIdx.x;
    const float* g  = (z == 0) ? g0 : (z == 1) ? g1 : g2;
    const float* be = (z == 0) ? be0 : (z == 1) ? be1 : be2;
    int wid  = threadIdx.x >> 5;
    int lane = threadIdx.x & 31;
    const float inv_cnt = 1.f / (float)ROWS;

#pragma unroll
    for (int i = 0; i < 8; i++) {
        int ch = wid * 8 + i;
        const float* ps = g_psum   + ((size_t)(zbase + z) * DCH + ch) * MBLK + lane * 12;
        const float* qs = g_psumsq + ((size_t)(zbase + z) * DCH + ch) * MBLK + lane * 12;
        float s = 0.f, s2 = 0.f;
#pragma unroll
        for (int j = 0; j < 3; j++) {
            float4 a = *(const float4*)(ps + j * 4);
            float4 b = *(const float4*)(qs + j * 4);
            s  += (a.x + a.y) + (a.z + a.w);
            s2 += (b.x + b.y) + (b.z + b.w);
        }
#pragma unroll
        for (int o = 16; o > 0; o >>= 1) {
            s  += __shfl_xor_sync(0xffffffffu, s, o);
            s2 += __shfl_xor_sync(0xffffffffu, s2, o);
        }
        if (lane == 0) {
            float mu  = s * inv_cnt;
            float var = s2 * inv_cnt - mu * mu;
            float sc  = g[ch] * rsqrtf(var + 1e-5f);
            g_scale[(zbase + z) * 128 + ch] = sc;
            g_shift[(zbase + z) * 128 + ch] = be[ch] - mu * sc;
        }
    }
}

// ---------------- dense tensor-core masked flash-attention v6 ---------------
// (unchanged from R11: 512 thr, QK tf32, PV split-bf16 no-transpose, ones-mma
// denominator, no-max softmax; measured component of the 374.6us run)
__global__ __launch_bounds__(512)
void attn_mma_kernel()
{
    extern __shared__ unsigned smu[];
    unsigned* Ktp = smu;                          // [16][KT2PAD]  K^T tf32 paired
    unsigned* Vh  = Ktp + 16 * KT2PAD;            // [128][VPPAD]  V hi bf16 paired
    unsigned* Vl  = Vh  + 128 * VPPAD;            // [128][VPPAD]  V lo bf16 paired
    unsigned* Asq = Vl  + 128 * VPPAD;            // [256][AQPAD]  Q tile tf32
    unsigned* smk = Asq + 256 * AQPAD;            // [512][16]     mask bitmap

    const int bt   = blockIdx.x;
    const int h    = blockIdx.y;
    const int tid  = threadIdx.x;
    const int lane = tid & 31;
    const int wid  = tid >> 5;                    // 0..15
    const int g    = lane >> 2;
    const int tg   = lane & 3;
    const size_t rowbase = (size_t)bt * NNODES;
    const int cb = h * 32;

    const float scq = g_scale[0 * 128 + cb + lane], shq = g_shift[0 * 128 + cb + lane];
    const float sck = g_scale[1 * 128 + cb + lane], shk = g_shift[1 * 128 + cb + lane];
    const float scv = g_scale[2 * 128 + cb + lane], shv = g_shift[2 * 128 + cb + lane];

    // stage K -> Ktp (tf32, channel-paired) and V -> Vh/Vl (bf16 split, paired)
    {
        const int c     = lane;
        const int krow  = (c >> 3) * 4 + (c & 3);
        const int khalf = (c & 7) >> 2;
        for (int idx = tid; idx < NNODES * 32; idx += 512) {
            int n = idx >> 5;                     // (idx & 31) == lane
            float kv = g_kraw[(rowbase + n) * 128 + cb + c];
            Ktp[krow * KT2PAD + 2 * n + khalf] =
                f2tf32(fmaxf(0.f, fmaf(kv, sck, shk)));
            float vv = g_vraw[(rowbase + n) * 128 + cb + c];
            float vfull = fmaxf(0.f, fmaf(vv, scv, shv));
            __nv_bfloat16 vhb = __float2bfloat16_rn(vfull);
            float vhf = __bfloat162float(vhb);
            __nv_bfloat16 vlb = __float2bfloat16_rn(vfull - vhf);
            int p = n >> 1, q = p & 7;
            int vofs = ((p >> 3) * 4 + (q & 3)) * VPPAD + 2 * c + (q >> 2);
            ((unsigned short*)&Vh[vofs])[n & 1] = *(unsigned short*)&vhb;
            ((unsigned short*)&Vl[vofs])[n & 1] = *(unsigned short*)&vlb;
        }
    }
    for (int idx = tid; idx < NNODES * 16; idx += 512) smk[idx] = g_mask[idx];
    __syncthreads();

    const int q0 = wid * 16;
    const float K1 = 0.72134752044f;   // log2(e)/2
    const float K0 = -43.2808512267f;  // -30*log2(e)
    const unsigned BONES0 = 0x3F803F80u;   // bf16 1.0 pair
    unsigned bones[2] = {BONES0, BONES0};

    for (int qt = 0; qt < 2; qt++) {
        for (int idx = tid; idx < 256 * 32; idx += 512) {
            int r = idx >> 5;
            float qv = g_qraw[(rowbase + qt * 256 + r) * 128 + cb + lane];
            Asq[r * AQPAD + lane] = f2tf32(fmaxf(0.f, fmaf(qv, scq, shq)));
        }
        __syncthreads();

        const int r0 = qt * 256 + q0 + g;
        const int r1 = r0 + 8;

        // hoist Q fragments (invariant across kv strips)
        unsigned aq[4][4];
#pragma unroll
        for (int ks = 0; ks < 4; ks++) {
            const int kb = ks * 8;
            aq[ks][0] = Asq[(q0 + g) * AQPAD + kb + tg];
            aq[ks][1] = Asq[(q0 + g + 8) * AQPAD + kb + tg];
            aq[ks][2] = Asq[(q0 + g) * AQPAD + kb + tg + 4];
            aq[ks][3] = Asq[(q0 + g + 8) * AQPAD + kb + tg + 4];
        }

        float o[4][4], o5[4];
#pragma unroll
        for (int nt = 0; nt < 4; nt++)
#pragma unroll
            for (int q = 0; q < 4; q++) o[nt][q] = 0.f;
        o5[0] = 0.f; o5[1] = 0.f; o5[2] = 0.f; o5[3] = 0.f;

        for (int kv = 0; kv < 16; kv++) {
            const int n0 = kv * 32;

            // ---- S = Q K^T (16x32 strip), paired LDS.64 B-frags ----
            float c[4][4];
#pragma unroll
            for (int nt = 0; nt < 4; nt++) {
                c[nt][0] = 0.f; c[nt][1] = 0.f; c[nt][2] = 0.f; c[nt][3] = 0.f;
            }
#pragma unroll
            for (int ks = 0; ks < 4; ks++) {
#pragma unroll
                for (int nt = 0; nt < 4; nt++) {
                    int cc = n0 + nt * 8 + g;
                    uint2 b2 = *(const uint2*)&Ktp[(ks * 4 + tg) * KT2PAD + 2 * cc];
                    unsigned b[2] = {b2.x, b2.y};
                    mma_tf32(c[nt], aq[ks], b);
                }
            }

            // ---- masked exp (no max tracking) ----
            unsigned w0 = smk[r0 * 16 + kv];
            unsigned w1 = smk[r1 * 16 + kv];
#pragma unroll
            for (int nt = 0; nt < 4; nt++) {
                int sh = nt * 8 + 2 * tg;
                c[nt][0] = ((w0 >> sh) & 1u)       ? ex2f(fmaf(c[nt][0], K1, K0)) : 0.f;
                c[nt][1] = ((w0 >> (sh + 1)) & 1u) ? ex2f(fmaf(c[nt][1], K1, K0)) : 0.f;
                c[nt][2] = ((w1 >> sh) & 1u)       ? ex2f(fmaf(c[nt][2], K1, K0)) : 0.f;
                c[nt][3] = ((w1 >> (sh + 1)) & 1u) ? ex2f(fmaf(c[nt][3], K1, K0)) : 0.f;
            }

            // ---- O += P V (split-bf16, no transpose); l via ones-mma ----
#pragma unroll
            for (int kt = 0; kt < 2; kt++) {
                unsigned ahi[4], alo[4];
                packsplit(c[2 * kt][0],     c[2 * kt][1],     ahi[0], alo[0]);
                packsplit(c[2 * kt][2],     c[2 * kt][3],     ahi[1], alo[1]);
                packsplit(c[2 * kt + 1][0], c[2 * kt + 1][1], ahi[2], alo[2]);
                packsplit(c[2 * kt + 1][2], c[2 * kt + 1][3], ahi[3], alo[3]);
                const int pblk = kv * 2 + kt;
#pragma unroll
                for (int nt = 0; nt < 4; nt++) {
                    int bofs = (pblk * 4 + tg) * VPPAD + 2 * (nt * 8 + g);
                    uint2 bh2 = *(const uint2*)&Vh[bofs];
                    uint2 bl2 = *(const uint2*)&Vl[bofs];
                    unsigned bh[2] = {bh2.x, bh2.y};
                    unsigned bl[2] = {bl2.x, bl2.y};
                    mma_bf16(o[nt], ahi, bh);
                    mma_bf16(o[nt], alo, bh);
                    mma_bf16(o[nt], ahi, bl);
                }
                mma_bf16(o5, ahi, bones);
                mma_bf16(o5, alo, bones);
            }
        }

        // ---- epilogue: normalize, write (o5[0]=l(row g), o5[2]=l(row g+8)) ----
        float il0 = 1.f / o5[0], il1 = 1.f / o5[2];
#pragma unroll
        for (int nt = 0; nt < 4; nt++) {
            int col = cb + nt * 8 + 2 * tg;
            *(float2*)&g_aout[(rowbase + r0) * 128 + col] =
                make_float2(o[nt][0] * il0, o[nt][1] * il0);
            *(float2*)&g_aout[(rowbase + r1) * 128 + col] =
                make_float2(o[nt][2] * il1, o[nt][3] * il1);
        }
        __syncthreads();   // before next qt re-stages Asq
    }
}

// ---------------- final BN+ReLU into d_out (float4) --------------------------
__global__ void bn_apply_kernel(float* __restrict__ out)
{
    size_t i4 = (size_t)blockIdx.x * blockDim.x + threadIdx.x;
    if (i4 >= (size_t)ROWS * DCH / 4) return;
    int c0 = (int)((i4 * 4) & 127);
    float4 v = *(const float4*)&g_oraw[i4 * 4];
    float4 sc = *(const float4*)&g_scale[3 * 128 + c0];
    float4 sh = *(const float4*)&g_shift[3 * 128 + c0];
    float4 r;
    r.x = fmaxf(0.f, fmaf(v.x, sc.x, sh.x));
    r.y = fmaxf(0.f, fmaf(v.y, sc.y, sh.y));
    r.z = fmaxf(0.f, fmaf(v.z, sc.z, sh.z));
    r.w = fmaxf(0.f, fmaf(v.w, sc.w, sh.w));
    *(float4*)&out[i4 * 4] = r;
}

// =============================================================================
extern "C" void kernel_launch(void* const* d_in, const int* in_sizes, int n_in,
                              void* d_out, int out_size)
{
    (void)in_sizes; (void)n_in; (void)out_size;
    const float* X     = (const float*)d_in[0];
    const float* STE   = (const float*)d_in[1];
    const float* A     = (const float*)d_in[2];
    const float* Wq    = (const float*)d_in[3];
    const float* gq    = (const float*)d_in[5];
    const float* betaq = (const float*)d_in[6];
    const float* Wk    = (const float*)d_in[7];
    const float* gk    = (const float*)d_in[9];
    const float* betak = (const float*)d_in[10];
    const float* Wv    = (const float*)d_in[11];
    const float* gv    = (const float*)d_in[13];
    const float* betav = (const float*)d_in[14];
    const float* Wo    = (const float*)d_in[15];
    const float* go    = (const float*)d_in[17];
    const float* betao = (const float*)d_in[18];
    float* out = (float*)d_out;

    void *pq, *pk, *pv, *pa, *po;
    cudaGetSymbolAddress(&pq, g_qraw);
    cudaGetSymbolAddress(&pk, g_kraw);
    cudaGetSymbolAddress(&pv, g_vraw);
    cudaGetSymbolAddress(&pa, g_aout);
    cudaGetSymbolAddress(&po, g_oraw);

    const int smem_attn = (16 * KT2PAD + 2 * 128 * VPPAD + 256 * AQPAD +
                           NNODES * 16) * (int)sizeof(unsigned);   // ~204.5 KB
    cudaFuncSetAttribute(attn_mma_kernel, cudaFuncAttributeMaxDynamicSharedMemorySize,
                         smem_attn);

    // 1) setup: adjacency bitmap + weight pre-split (one launch)
    setup_kernel<<<16 + (WTOTAL + 1023) / 1024, 1024>>>(A, Wq, Wk, Wv, Wo);

    // 2) q/k/v projections (split-bf16 3-term, pre-split W, fused BN stats)
    mma_gemm_kernel<256, true><<<dim3(MBLK, 1, 3), 256>>>(
        X, STE, 0, 16384, (float*)pq, (float*)pk, (float*)pv, 0);

    // 3) BN finalize for q/k/v (warp-per-channel, ~2us)
    bn_finalize_kernel<<<3, 512>>>(gq, betaq, gk, betak, gv, betav, 0);

    // 4) dense tensor-core masked attention v6 (split-bf16 PV, ones-mma l)
    attn_mma_kernel<<<dim3(NBT, NH), 512, smem_attn>>>();

    // 5) output projection (split-bf16 3-term, pre-split W, fused BN stats)
    mma_gemm_kernel<128, false><<<dim3(MBLK, 1, 1), 256>>>(
        (float*)pa, nullptr, WOFF_O, 0, (float*)po, (float*)po, (float*)po, 3);

    // 6) BN finalize for output
    bn_finalize_kernel<<<1, 512>>>(go, betao, go, betao, go, betao, 3);

    // 7) BN + ReLU -> d_out
    bn_apply_kernel<<<(ROWS * DCH / 4 + 255) / 256, 256>>>(out);
}